// round 3
// baseline (speedup 1.0000x reference)
#include <cuda_runtime.h>

// Problem constants
#define BB   2
#define SS   2048
#define HID  1024
#define NH   16
#define DH   64
#define ROT  32

// Scratch (device globals; no allocations allowed)
__device__ float g_Q[BB * NH * SS * DH];   // query, rotary+scale applied, [b][h][s][d]
__device__ float g_K[BB * NH * SS * DH];   // key, rotary applied
__device__ float g_V[BB * NH * SS * DH];   // value
__device__ float g_ctx[BB * SS * HID];     // attention output, [b][s][h*64+d]

// ---------------------------------------------------------------------------
// Kernel 1: QKV GEMM  x[4096,1024] @ w[1024,3072] -> fused bias+rotary+scatter
// ---------------------------------------------------------------------------
__global__ __launch_bounds__(256) void qkv_gemm_kernel(
    const float* __restrict__ x, const float* __restrict__ w,
    const float* __restrict__ qbias, const float* __restrict__ sinu)
{
    __shared__ float As[16][68];   // [k][m], padded
    __shared__ float Bs[16][64];   // [k][n]
    const int tid = threadIdx.x, ty = tid >> 4, tx = tid & 15;
    const int bm = blockIdx.y * 64, bn = blockIdx.x * 64;
    const int N = 3 * NH * DH;     // 3072
    const int K = HID;             // 1024

    float acc[4][4] = {};

    for (int k0 = 0; k0 < K; k0 += 16) {
        #pragma unroll
        for (int t = 0; t < 4; ++t) {
            int idx = tid + t * 256;
            int r = idx >> 4, c = idx & 15;
            As[c][r] = x[(size_t)(bm + r) * K + k0 + c];
        }
        {
            int kr = tid >> 4, c4 = tid & 15;
            ((float4*)&Bs[kr][0])[c4] =
                ((const float4*)&w[(size_t)(k0 + kr) * N + bn])[c4];
        }
        __syncthreads();
        #pragma unroll
        for (int k = 0; k < 16; ++k) {
            float4 a4 = *(const float4*)&As[k][ty * 4];
            float4 b4 = *(const float4*)&Bs[k][tx * 4];
            float av[4] = {a4.x, a4.y, a4.z, a4.w};
            float bv[4] = {b4.x, b4.y, b4.z, b4.w};
            #pragma unroll
            for (int i = 0; i < 4; ++i)
                #pragma unroll
                for (int j = 0; j < 4; ++j)
                    acc[i][j] += av[i] * bv[j];
        }
        __syncthreads();
    }

    // Epilogue: bias + rotary (+ query scale), scatter to Q/K/V
    const int head = bn >> 6;  // constant per block (bn multiple of 64)
    #pragma unroll
    for (int i = 0; i < 4; ++i) {
        int m = bm + ty * 4 + i;
        int b = m >> 11;            // m / SS
        int s = m & (SS - 1);
        #pragma unroll
        for (int j = 0; j < 4; ++j) {
            int d = tx * 4 + j;
            float v = acc[i][j] + qbias[head * DH + d];
            if (head < 2 * NH && d < ROT) {
                float sn = sinu[s * ROT + d];
                float cs = sinu[SS * ROT + s * ROT + d];
                v *= (d & 1) ? (cs + sn) : (cs - sn);
            }
            if (head < NH) {
                g_Q[(((size_t)(b * NH + head) * SS) + s) * DH + d] = v * 0.125f;
            } else if (head < 2 * NH) {
                g_K[(((size_t)(b * NH + head - NH) * SS) + s) * DH + d] = v;
            } else {
                g_V[(((size_t)(b * NH + head - 2 * NH) * SS) + s) * DH + d] = v;
            }
        }
    }
}

// ---------------------------------------------------------------------------
// Kernel 2: flash attention. CTA = (q-tile of 64, head, batch). 256 threads.
// Thread (ty,tx): rows ty*4+i, cols tx+16*j.
// SMEM: Qs[64][68], Ks[64][68] (reused for P), Vs[64][68]  -> 52224 B dynamic
// ---------------------------------------------------------------------------
__global__ __launch_bounds__(256) void flash_kernel(const float* __restrict__ bias)
{
    extern __shared__ float sm[];
    float* Qs = sm;                // [64][68]
    float* Ks = sm + 64 * 68;      // [64][68], later holds P
    float* Vs = sm + 2 * 64 * 68;  // [64][68]

    const int tid = threadIdx.x, ty = tid >> 4, tx = tid & 15;
    const int qt = blockIdx.x, h = blockIdx.y, b = blockIdx.z;

    const float* Qg = g_Q + ((size_t)(b * NH + h) * SS + qt * 64) * DH;
    const float* Kg = g_K + (size_t)(b * NH + h) * SS * DH;
    const float* Vg = g_V + (size_t)(b * NH + h) * SS * DH;
    const float* bg = bias + ((size_t)b * SS + qt * 64) * SS;

    // Load Q tile
    {
        const float4* q4 = (const float4*)Qg;
        #pragma unroll
        for (int t = 0; t < 4; ++t) {
            int idx = tid + t * 256;
            int r = idx >> 4, c = idx & 15;
            *(float4*)&Qs[r * 68 + c * 4] = q4[idx];
        }
    }

    float m_i[4], l_i[4], o[4][4];
    #pragma unroll
    for (int i = 0; i < 4; ++i) {
        m_i[i] = -1e30f; l_i[i] = 0.f;
        #pragma unroll
        for (int j = 0; j < 4; ++j) o[i][j] = 0.f;
    }

    for (int kt = 0; kt < SS / 64; ++kt) {
        __syncthreads();  // previous iteration done with Ks(P)/Vs
        {
            const float4* k4 = (const float4*)(Kg + (size_t)kt * 64 * DH);
            const float4* v4 = (const float4*)(Vg + (size_t)kt * 64 * DH);
            #pragma unroll
            for (int t = 0; t < 4; ++t) {
                int idx = tid + t * 256;
                int r = idx >> 4, c = idx & 15;
                *(float4*)&Ks[r * 68 + c * 4] = k4[idx];
                *(float4*)&Vs[r * 68 + c * 4] = v4[idx];
            }
        }
        __syncthreads();

        // s = bias + q.k  (scale pre-folded into Q)
        float s[4][4];
        #pragma unroll
        for (int i = 0; i < 4; ++i)
            #pragma unroll
            for (int j = 0; j < 4; ++j)
                s[i][j] = __ldg(&bg[(size_t)(ty * 4 + i) * SS + kt * 64 + tx + 16 * j]);

        #pragma unroll 8
        for (int d = 0; d < 64; ++d) {
            float qv[4], kv[4];
            #pragma unroll
            for (int i = 0; i < 4; ++i) qv[i] = Qs[(ty * 4 + i) * 68 + d];
            #pragma unroll
            for (int j = 0; j < 4; ++j) kv[j] = Ks[(tx + 16 * j) * 68 + d];
            #pragma unroll
            for (int i = 0; i < 4; ++i)
                #pragma unroll
                for (int j = 0; j < 4; ++j)
                    s[i][j] += qv[i] * kv[j];
        }

        // online softmax (row reductions across the 16 tx lanes)
        #pragma unroll
        for (int i = 0; i < 4; ++i) {
            float mx = fmaxf(fmaxf(s[i][0], s[i][1]), fmaxf(s[i][2], s[i][3]));
            #pragma unroll
            for (int w = 1; w < 16; w <<= 1)
                mx = fmaxf(mx, __shfl_xor_sync(0xffffffffu, mx, w));
            float mnew = fmaxf(m_i[i], mx);
            float ps = 0.f;
            #pragma unroll
            for (int j = 0; j < 4; ++j) {
                s[i][j] = __expf(s[i][j] - mnew);
                ps += s[i][j];
            }
            #pragma unroll
            for (int w = 1; w < 16; w <<= 1)
                ps += __shfl_xor_sync(0xffffffffu, ps, w);
            float corr = __expf(m_i[i] - mnew);
            l_i[i] = l_i[i] * corr + ps;
            m_i[i] = mnew;
            #pragma unroll
            for (int j = 0; j < 4; ++j) o[i][j] *= corr;
        }

        __syncthreads();  // everyone done reading Ks
        #pragma unroll
        for (int i = 0; i < 4; ++i)
            #pragma unroll
            for (int j = 0; j < 4; ++j)
                Ks[(ty * 4 + i) * 68 + tx + 16 * j] = s[i][j];   // P tile
        __syncthreads();

        // o += P @ V
        #pragma unroll 8
        for (int k = 0; k < 64; ++k) {
            float pv[4], vv[4];
            #pragma unroll
            for (int i = 0; i < 4; ++i) pv[i] = Ks[(ty * 4 + i) * 68 + k];
            #pragma unroll
            for (int j = 0; j < 4; ++j) vv[j] = Vs[k * 68 + tx + 16 * j];
            #pragma unroll
            for (int i = 0; i < 4; ++i)
                #pragma unroll
                for (int j = 0; j < 4; ++j)
                    o[i][j] += pv[i] * vv[j];
        }
    }

    // normalize and write ctx as [b][s][h][d]
    #pragma unroll
    for (int i = 0; i < 4; ++i) {
        float inv = 1.0f / l_i[i];
        int q = qt * 64 + ty * 4 + i;
        float* dst = g_ctx + ((size_t)(b * SS + q) * NH + h) * DH;
        #pragma unroll
        for (int j = 0; j < 4; ++j)
            dst[tx + 16 * j] = o[i][j] * inv;
    }
}

// ---------------------------------------------------------------------------
// Kernel 3: output projection  ctx[4096,1024] @ proj[1024,1024] -> out
// ---------------------------------------------------------------------------
__global__ __launch_bounds__(256) void proj_gemm_kernel(
    const float* __restrict__ w, float* __restrict__ out)
{
    __shared__ float As[16][68];
    __shared__ float Bs[16][64];
    const int tid = threadIdx.x, ty = tid >> 4, tx = tid & 15;
    const int bm = blockIdx.y * 64, bn = blockIdx.x * 64;
    const int N = HID, K = HID;

    float acc[4][4] = {};

    for (int k0 = 0; k0 < K; k0 += 16) {
        #pragma unroll
        for (int t = 0; t < 4; ++t) {
            int idx = tid + t * 256;
            int r = idx >> 4, c = idx & 15;
            As[c][r] = g_ctx[(size_t)(bm + r) * K + k0 + c];
        }
        {
            int kr = tid >> 4, c4 = tid & 15;
            ((float4*)&Bs[kr][0])[c4] =
                ((const float4*)&w[(size_t)(k0 + kr) * N + bn])[c4];
        }
        __syncthreads();
        #pragma unroll
        for (int k = 0; k < 16; ++k) {
            float4 a4 = *(const float4*)&As[k][ty * 4];
            float4 b4 = *(const float4*)&Bs[k][tx * 4];
            float av[4] = {a4.x, a4.y, a4.z, a4.w};
            float bv[4] = {b4.x, b4.y, b4.z, b4.w};
            #pragma unroll
            for (int i = 0; i < 4; ++i)
                #pragma unroll
                for (int j = 0; j < 4; ++j)
                    acc[i][j] += av[i] * bv[j];
        }
        __syncthreads();
    }

    #pragma unroll
    for (int i = 0; i < 4; ++i) {
        float4 r = make_float4(acc[i][0], acc[i][1], acc[i][2], acc[i][3]);
        *(float4*)&out[(size_t)(bm + ty * 4 + i) * N + bn + tx * 4] = r;
    }
}

// ---------------------------------------------------------------------------
extern "C" void kernel_launch(void* const* d_in, const int* in_sizes, int n_in,
                              void* d_out, int out_size)
{
    const float* x      = (const float*)d_in[0];
    const float* sinu   = (const float*)d_in[1];
    const float* abias  = (const float*)d_in[2];
    const float* qkv_w  = (const float*)d_in[3];
    const float* qkv_b  = (const float*)d_in[4];
    const float* proj_w = (const float*)d_in[5];
    float* out = (float*)d_out;

    const int flash_smem = 3 * 64 * 68 * (int)sizeof(float);  // 52224 B
    cudaFuncSetAttribute(flash_kernel,
                         cudaFuncAttributeMaxDynamicSharedMemorySize, flash_smem);

    dim3 blk(256);
    qkv_gemm_kernel<<<dim3(48, 64), blk>>>(x, qkv_w, qkv_b, sinu);
    flash_kernel<<<dim3(SS / 64, NH, BB), blk, flash_smem>>>(abias);
    proj_gemm_kernel<<<dim3(16, 64), blk>>>(proj_w, out);
}

// round 4
// speedup vs baseline: 1.0006x; 1.0006x over previous
#include <cuda_runtime.h>

// Problem constants
#define BB   2
#define SS   2048
#define HID  1024
#define NH   16
#define DH   64
#define ROT  32

// Scratch (device globals; no allocations allowed)
__device__ float g_Q[BB * NH * SS * DH];   // query, rotary+scale applied, [b][h][s][d]
__device__ float g_K[BB * NH * SS * DH];   // key, rotary applied
__device__ float g_V[BB * NH * SS * DH];   // value
__device__ float g_ctx[BB * SS * HID];     // attention output, [b][s][h*64+d]

// ---------------------------------------------------------------------------
// Kernel 1: QKV GEMM  x[4096,1024] @ w[1024,3072] -> fused bias+rotary+scatter
// ---------------------------------------------------------------------------
__global__ __launch_bounds__(256) void qkv_gemm_kernel(
    const float* __restrict__ x, const float* __restrict__ w,
    const float* __restrict__ qbias, const float* __restrict__ sinu)
{
    __shared__ float As[16][68];   // [k][m], padded
    __shared__ float Bs[16][64];   // [k][n]
    const int tid = threadIdx.x, ty = tid >> 4, tx = tid & 15;
    const int bm = blockIdx.y * 64, bn = blockIdx.x * 64;
    const int N = 3 * NH * DH;     // 3072
    const int K = HID;             // 1024

    float acc[4][4] = {};

    for (int k0 = 0; k0 < K; k0 += 16) {
        #pragma unroll
        for (int t = 0; t < 4; ++t) {
            int idx = tid + t * 256;
            int r = idx >> 4, c = idx & 15;
            As[c][r] = x[(size_t)(bm + r) * K + k0 + c];
        }
        {
            int kr = tid >> 4, c4 = tid & 15;
            ((float4*)&Bs[kr][0])[c4] =
                ((const float4*)&w[(size_t)(k0 + kr) * N + bn])[c4];
        }
        __syncthreads();
        #pragma unroll
        for (int k = 0; k < 16; ++k) {
            float4 a4 = *(const float4*)&As[k][ty * 4];
            float4 b4 = *(const float4*)&Bs[k][tx * 4];
            float av[4] = {a4.x, a4.y, a4.z, a4.w};
            float bv[4] = {b4.x, b4.y, b4.z, b4.w};
            #pragma unroll
            for (int i = 0; i < 4; ++i)
                #pragma unroll
                for (int j = 0; j < 4; ++j)
                    acc[i][j] += av[i] * bv[j];
        }
        __syncthreads();
    }

    // Epilogue: bias + rotary (+ query scale), scatter to Q/K/V
    const int head = bn >> 6;  // constant per block (bn multiple of 64)
    #pragma unroll
    for (int i = 0; i < 4; ++i) {
        int m = bm + ty * 4 + i;
        int b = m >> 11;            // m / SS
        int s = m & (SS - 1);
        #pragma unroll
        for (int j = 0; j < 4; ++j) {
            int d = tx * 4 + j;
            float v = acc[i][j] + qbias[head * DH + d];
            if (head < 2 * NH && d < ROT) {
                float sn = sinu[s * ROT + d];
                float cs = sinu[SS * ROT + s * ROT + d];
                v *= (d & 1) ? (cs + sn) : (cs - sn);
            }
            if (head < NH) {
                g_Q[(((size_t)(b * NH + head) * SS) + s) * DH + d] = v * 0.125f;
            } else if (head < 2 * NH) {
                g_K[(((size_t)(b * NH + head - NH) * SS) + s) * DH + d] = v;
            } else {
                g_V[(((size_t)(b * NH + head - 2 * NH) * SS) + s) * DH + d] = v;
            }
        }
    }
}

// ---------------------------------------------------------------------------
// Kernel 2: flash attention. CTA = (q-tile of 64, head, batch). 256 threads.
// Thread (ty,tx): rows ty*4+i, cols tx+16*j.
// SMEM: Qs[64][68], Ks[64][68] (reused for P), Vs[64][68]  -> 52224 B dynamic
// ---------------------------------------------------------------------------
__global__ __launch_bounds__(256) void flash_kernel(const float* __restrict__ bias)
{
    extern __shared__ float sm[];
    float* Qs = sm;                // [64][68]
    float* Ks = sm + 64 * 68;      // [64][68], later holds P
    float* Vs = sm + 2 * 64 * 68;  // [64][68]

    const int tid = threadIdx.x, ty = tid >> 4, tx = tid & 15;
    const int qt = blockIdx.x, h = blockIdx.y, b = blockIdx.z;

    const float* Qg = g_Q + ((size_t)(b * NH + h) * SS + qt * 64) * DH;
    const float* Kg = g_K + (size_t)(b * NH + h) * SS * DH;
    const float* Vg = g_V + (size_t)(b * NH + h) * SS * DH;
    const float* bg = bias + ((size_t)b * SS + qt * 64) * SS;

    // Load Q tile
    {
        const float4* q4 = (const float4*)Qg;
        #pragma unroll
        for (int t = 0; t < 4; ++t) {
            int idx = tid + t * 256;
            int r = idx >> 4, c = idx & 15;
            *(float4*)&Qs[r * 68 + c * 4] = q4[idx];
        }
    }

    float m_i[4], l_i[4], o[4][4];
    #pragma unroll
    for (int i = 0; i < 4; ++i) {
        m_i[i] = -1e30f; l_i[i] = 0.f;
        #pragma unroll
        for (int j = 0; j < 4; ++j) o[i][j] = 0.f;
    }

    for (int kt = 0; kt < SS / 64; ++kt) {
        __syncthreads();  // previous iteration done with Ks(P)/Vs
        {
            const float4* k4 = (const float4*)(Kg + (size_t)kt * 64 * DH);
            const float4* v4 = (const float4*)(Vg + (size_t)kt * 64 * DH);
            #pragma unroll
            for (int t = 0; t < 4; ++t) {
                int idx = tid + t * 256;
                int r = idx >> 4, c = idx & 15;
                *(float4*)&Ks[r * 68 + c * 4] = k4[idx];
                *(float4*)&Vs[r * 68 + c * 4] = v4[idx];
            }
        }
        __syncthreads();

        // s = bias + q.k  (scale pre-folded into Q)
        float s[4][4];
        #pragma unroll
        for (int i = 0; i < 4; ++i)
            #pragma unroll
            for (int j = 0; j < 4; ++j)
                s[i][j] = __ldg(&bg[(size_t)(ty * 4 + i) * SS + kt * 64 + tx + 16 * j]);

        #pragma unroll 8
        for (int d = 0; d < 64; ++d) {
            float qv[4], kv[4];
            #pragma unroll
            for (int i = 0; i < 4; ++i) qv[i] = Qs[(ty * 4 + i) * 68 + d];
            #pragma unroll
            for (int j = 0; j < 4; ++j) kv[j] = Ks[(tx + 16 * j) * 68 + d];
            #pragma unroll
            for (int i = 0; i < 4; ++i)
                #pragma unroll
                for (int j = 0; j < 4; ++j)
                    s[i][j] += qv[i] * kv[j];
        }

        // online softmax (row reductions across the 16 tx lanes)
        #pragma unroll
        for (int i = 0; i < 4; ++i) {
            float mx = fmaxf(fmaxf(s[i][0], s[i][1]), fmaxf(s[i][2], s[i][3]));
            #pragma unroll
            for (int w = 1; w < 16; w <<= 1)
                mx = fmaxf(mx, __shfl_xor_sync(0xffffffffu, mx, w));
            float mnew = fmaxf(m_i[i], mx);
            float ps = 0.f;
            #pragma unroll
            for (int j = 0; j < 4; ++j) {
                s[i][j] = __expf(s[i][j] - mnew);
                ps += s[i][j];
            }
            #pragma unroll
            for (int w = 1; w < 16; w <<= 1)
                ps += __shfl_xor_sync(0xffffffffu, ps, w);
            float corr = __expf(m_i[i] - mnew);
            l_i[i] = l_i[i] * corr + ps;
            m_i[i] = mnew;
            #pragma unroll
            for (int j = 0; j < 4; ++j) o[i][j] *= corr;
        }

        __syncthreads();  // everyone done reading Ks
        #pragma unroll
        for (int i = 0; i < 4; ++i)
            #pragma unroll
            for (int j = 0; j < 4; ++j)
                Ks[(ty * 4 + i) * 68 + tx + 16 * j] = s[i][j];   // P tile
        __syncthreads();

        // o += P @ V
        #pragma unroll 8
        for (int k = 0; k < 64; ++k) {
            float pv[4], vv[4];
            #pragma unroll
            for (int i = 0; i < 4; ++i) pv[i] = Ks[(ty * 4 + i) * 68 + k];
            #pragma unroll
            for (int j = 0; j < 4; ++j) vv[j] = Vs[k * 68 + tx + 16 * j];
            #pragma unroll
            for (int i = 0; i < 4; ++i)
                #pragma unroll
                for (int j = 0; j < 4; ++j)
                    o[i][j] += pv[i] * vv[j];
        }
    }

    // normalize and write ctx as [b][s][h][d]
    #pragma unroll
    for (int i = 0; i < 4; ++i) {
        float inv = 1.0f / l_i[i];
        int q = qt * 64 + ty * 4 + i;
        float* dst = g_ctx + ((size_t)(b * SS + q) * NH + h) * DH;
        #pragma unroll
        for (int j = 0; j < 4; ++j)
            dst[tx + 16 * j] = o[i][j] * inv;
    }
}

// ---------------------------------------------------------------------------
// Kernel 3: output projection  ctx[4096,1024] @ proj[1024,1024] -> out
// ---------------------------------------------------------------------------
__global__ __launch_bounds__(256) void proj_gemm_kernel(
    const float* __restrict__ w, float* __restrict__ out)
{
    __shared__ float As[16][68];
    __shared__ float Bs[16][64];
    const int tid = threadIdx.x, ty = tid >> 4, tx = tid & 15;
    const int bm = blockIdx.y * 64, bn = blockIdx.x * 64;
    const int N = HID, K = HID;

    float acc[4][4] = {};

    for (int k0 = 0; k0 < K; k0 += 16) {
        #pragma unroll
        for (int t = 0; t < 4; ++t) {
            int idx = tid + t * 256;
            int r = idx >> 4, c = idx & 15;
            As[c][r] = g_ctx[(size_t)(bm + r) * K + k0 + c];
        }
        {
            int kr = tid >> 4, c4 = tid & 15;
            ((float4*)&Bs[kr][0])[c4] =
                ((const float4*)&w[(size_t)(k0 + kr) * N + bn])[c4];
        }
        __syncthreads();
        #pragma unroll
        for (int k = 0; k < 16; ++k) {
            float4 a4 = *(const float4*)&As[k][ty * 4];
            float4 b4 = *(const float4*)&Bs[k][tx * 4];
            float av[4] = {a4.x, a4.y, a4.z, a4.w};
            float bv[4] = {b4.x, b4.y, b4.z, b4.w};
            #pragma unroll
            for (int i = 0; i < 4; ++i)
                #pragma unroll
                for (int j = 0; j < 4; ++j)
                    acc[i][j] += av[i] * bv[j];
        }
        __syncthreads();
    }

    #pragma unroll
    for (int i = 0; i < 4; ++i) {
        float4 r = make_float4(acc[i][0], acc[i][1], acc[i][2], acc[i][3]);
        *(float4*)&out[(size_t)(bm + ty * 4 + i) * N + bn + tx * 4] = r;
    }
}

// ---------------------------------------------------------------------------
extern "C" void kernel_launch(void* const* d_in, const int* in_sizes, int n_in,
                              void* d_out, int out_size)
{
    const float* x      = (const float*)d_in[0];
    const float* sinu   = (const float*)d_in[1];
    const float* abias  = (const float*)d_in[2];
    const float* qkv_w  = (const float*)d_in[3];
    const float* qkv_b  = (const float*)d_in[4];
    const float* proj_w = (const float*)d_in[5];
    float* out = (float*)d_out;

    const int flash_smem = 3 * 64 * 68 * (int)sizeof(float);  // 52224 B
    cudaFuncSetAttribute(flash_kernel,
                         cudaFuncAttributeMaxDynamicSharedMemorySize, flash_smem);

    dim3 blk(256);
    qkv_gemm_kernel<<<dim3(48, 64), blk>>>(x, qkv_w, qkv_b, sinu);
    flash_kernel<<<dim3(SS / 64, NH, BB), blk, flash_smem>>>(abias);
    proj_gemm_kernel<<<dim3(16, 64), blk>>>(proj_w, out);
}

// round 5
// speedup vs baseline: 2.6272x; 2.6255x over previous
#include <cuda_runtime.h>

// Problem constants
#define BB   2
#define SS   2048
#define HID  1024
#define NH   16
#define DH   64
#define ROT  32

// Scratch (device globals; no allocations allowed)
__device__ float g_Q[BB * NH * SS * DH];   // query, rotary+scale applied, [b][h][s][d]
__device__ float g_K[BB * NH * SS * DH];   // key, rotary applied
__device__ float g_V[BB * NH * SS * DH];   // value
__device__ float g_ctx[BB * SS * HID];     // attention output, [b][s][h*64+d]

// ---------------------------------------------------------------------------
// tf32 helpers
// ---------------------------------------------------------------------------
__device__ __forceinline__ unsigned f2tf(float x) {
    unsigned u;
    asm("cvt.rna.tf32.f32 %0, %1;" : "=r"(u) : "f"(x));
    return u;
}

// D += A(16x8) * B(8x8), tf32 inputs, fp32 accum.
// A frag: a0=(g,t) a1=(g+8,t) a2=(g,t+4) a3=(g+8,t+4)   [g=lane>>2, t=lane&3]
// B frag: b0=(k=t,n=g) b1=(k=t+4,n=g)
// C frag: c0=(g,2t) c1=(g,2t+1) c2=(g+8,2t) c3=(g+8,2t+1)
__device__ __forceinline__ void mma_tf32(float* d, const unsigned* a, const unsigned* b) {
    asm volatile("mma.sync.aligned.m16n8k8.row.col.f32.tf32.tf32.f32 "
                 "{%0,%1,%2,%3}, {%4,%5,%6,%7}, {%8,%9}, {%0,%1,%2,%3};\n"
                 : "+f"(d[0]), "+f"(d[1]), "+f"(d[2]), "+f"(d[3])
                 : "r"(a[0]), "r"(a[1]), "r"(a[2]), "r"(a[3]),
                   "r"(b[0]), "r"(b[1]));
}

#define LDA 36   // pad for conflict-free (4g+t) A-frag loads
#define LDB 136  // pad for conflict-free (8t+g) B-frag loads

// ---------------------------------------------------------------------------
// tf32 GEMM template: C[4096,N] = A[4096,1024] @ W[1024,N]
// Block 128x128, Ktile 32, 256 threads = 8 warps (2 x 4), warp tile 64x32.
// QKV_EPI: fused bias + rotary + Q/K/V scatter. else: plain store to Cout.
// ---------------------------------------------------------------------------
template<int N, bool QKV_EPI>
__global__ __launch_bounds__(256) void gemm128_tf32(
    const float* __restrict__ Ain, const float* __restrict__ Wt,
    const float* __restrict__ qbias, const float* __restrict__ sinu,
    float* __restrict__ Cout)
{
    __shared__ unsigned As[128 * LDA];
    __shared__ unsigned Bs[32 * LDB];
    const int tid = threadIdx.x;
    const int lane = tid & 31, warp = tid >> 5;
    const int g = lane >> 2, t = lane & 3;
    const int wm = warp >> 2, wn = warp & 3;       // 2 (M) x 4 (N)
    const int bm = blockIdx.y * 128, bn = blockIdx.x * 128;
    const int K = HID;

    const float* A = QKV_EPI ? Ain : (const float*)g_ctx;

    float acc[4][4][4] = {};                       // [mtile][ntile][creg]

    for (int k0 = 0; k0 < K; k0 += 32) {
        // A tile 128x32 (row-major, ld=LDA), converted to tf32
        #pragma unroll
        for (int tt = 0; tt < 4; ++tt) {
            int e = tid + tt * 256;
            int r = e >> 3, c4 = (e & 7) * 4;
            float4 v = *(const float4*)&A[(size_t)(bm + r) * K + k0 + c4];
            *(uint4*)&As[r * LDA + c4] =
                make_uint4(f2tf(v.x), f2tf(v.y), f2tf(v.z), f2tf(v.w));
        }
        // B tile 32x128 (k-major, ld=LDB)
        #pragma unroll
        for (int tt = 0; tt < 4; ++tt) {
            int e = tid + tt * 256;
            int r = e >> 5, c4 = (e & 31) * 4;
            float4 v = *(const float4*)&Wt[(size_t)(k0 + r) * N + bn + c4];
            *(uint4*)&Bs[r * LDB + c4] =
                make_uint4(f2tf(v.x), f2tf(v.y), f2tf(v.z), f2tf(v.w));
        }
        __syncthreads();

        #pragma unroll
        for (int ks = 0; ks < 4; ++ks) {
            const int kk = ks * 8;
            unsigned af[4][4], bf[4][2];
            #pragma unroll
            for (int i = 0; i < 4; ++i) {
                int r0 = wm * 64 + i * 16 + g;
                af[i][0] = As[r0 * LDA + kk + t];
                af[i][1] = As[(r0 + 8) * LDA + kk + t];
                af[i][2] = As[r0 * LDA + kk + t + 4];
                af[i][3] = As[(r0 + 8) * LDA + kk + t + 4];
            }
            #pragma unroll
            for (int j = 0; j < 4; ++j) {
                int n = wn * 32 + j * 8 + g;
                bf[j][0] = Bs[(kk + t) * LDB + n];
                bf[j][1] = Bs[(kk + t + 4) * LDB + n];
            }
            #pragma unroll
            for (int i = 0; i < 4; ++i)
                #pragma unroll
                for (int j = 0; j < 4; ++j)
                    mma_tf32(acc[i][j], af[i], bf[j]);
        }
        __syncthreads();
    }

    // Epilogue
    #pragma unroll
    for (int i = 0; i < 4; ++i) {
        int r0 = bm + wm * 64 + i * 16 + g;
        #pragma unroll
        for (int j = 0; j < 4; ++j) {
            int c = bn + wn * 32 + j * 8 + 2 * t;
            if (QKV_EPI) {
                #pragma unroll
                for (int e = 0; e < 4; ++e) {
                    int r = r0 + (e >> 1) * 8;
                    int cc = c + (e & 1);
                    float v = acc[i][j][e] + qbias[cc];
                    int head = cc >> 6, d = cc & 63;
                    int b = r >> 11, s = r & (SS - 1);
                    if (head < 2 * NH && d < ROT) {
                        float sn = sinu[s * ROT + d];
                        float cs = sinu[SS * ROT + s * ROT + d];
                        v *= (d & 1) ? (cs + sn) : (cs - sn);
                    }
                    if (head < NH)
                        g_Q[(((size_t)(b * NH + head) * SS) + s) * DH + d] = v * 0.125f;
                    else if (head < 2 * NH)
                        g_K[(((size_t)(b * NH + head - NH) * SS) + s) * DH + d] = v;
                    else
                        g_V[(((size_t)(b * NH + head - 2 * NH) * SS) + s) * DH + d] = v;
                }
            } else {
                *(float2*)&Cout[(size_t)r0 * N + c] =
                    make_float2(acc[i][j][0], acc[i][j][1]);
                *(float2*)&Cout[(size_t)(r0 + 8) * N + c] =
                    make_float2(acc[i][j][2], acc[i][j][3]);
            }
        }
    }
}

// ---------------------------------------------------------------------------
// Flash attention, tf32 tensor cores. CTA = (q-tile 64, head, batch).
// 128 threads = 4 warps; warp w owns S rows [w*16, w*16+16), all 64 cols.
// mma tiling: 1 (M) x 8 (N) tiles, 8 k-steps over DH=64.
// SMEM (dynamic): Qs[64][68], Ks[64][68] (reused for P), Vs[64][68] = 52224 B
// ---------------------------------------------------------------------------
__global__ __launch_bounds__(128) void flash_tf32(const float* __restrict__ bias)
{
    extern __shared__ unsigned sm_u[];
    unsigned* Qs = sm_u;
    unsigned* Ks = sm_u + 64 * 68;
    unsigned* Vs = sm_u + 2 * 64 * 68;

    const int tid = threadIdx.x, lane = tid & 31, w = tid >> 5;
    const int g = lane >> 2, t = lane & 3;
    const int qt = blockIdx.x, h = blockIdx.y, b = blockIdx.z;

    const float* Qg = g_Q + ((size_t)(b * NH + h) * SS + qt * 64) * DH;
    const float* Kg = g_K + (size_t)(b * NH + h) * SS * DH;
    const float* Vg = g_V + (size_t)(b * NH + h) * SS * DH;
    const float* bg = bias + ((size_t)b * SS + qt * 64) * SS;

    // Load Q tile (tf32)
    #pragma unroll
    for (int tt = 0; tt < 8; ++tt) {
        int e = tid + tt * 128;
        int r = e >> 4, c4 = (e & 15) * 4;
        float4 v = *(const float4*)&Qg[r * 64 + c4];
        *(uint4*)&Qs[r * 68 + c4] =
            make_uint4(f2tf(v.x), f2tf(v.y), f2tf(v.z), f2tf(v.w));
    }

    const int row0 = w * 16 + g;          // this thread's first S row (in-tile)
    float m0 = -1e30f, m1 = -1e30f, l0 = 0.f, l1 = 0.f;
    float o[8][4] = {};                   // O accum, C-frag layout over 8 d-tiles

    for (int kt = 0; kt < SS / 64; ++kt) {
        __syncthreads();                  // prior iter done with Ks(P)/Vs
        #pragma unroll
        for (int tt = 0; tt < 8; ++tt) {
            int e = tid + tt * 128;
            int r = e >> 4, c4 = (e & 15) * 4;
            float4 kv = *(const float4*)&Kg[(size_t)kt * 64 * 64 + r * 64 + c4];
            float4 vv = *(const float4*)&Vg[(size_t)kt * 64 * 64 + r * 64 + c4];
            *(uint4*)&Ks[r * 68 + c4] =
                make_uint4(f2tf(kv.x), f2tf(kv.y), f2tf(kv.z), f2tf(kv.w));
            *(uint4*)&Vs[r * 68 + c4] =
                make_uint4(f2tf(vv.x), f2tf(vv.y), f2tf(vv.z), f2tf(vv.w));
        }
        __syncthreads();

        // S init from bias (C-frag positions)
        float s[8][4];
        #pragma unroll
        for (int n = 0; n < 8; ++n) {
            int c = kt * 64 + n * 8 + 2 * t;
            float2 b0v = *(const float2*)&bg[(size_t)row0 * SS + c];
            float2 b1v = *(const float2*)&bg[(size_t)(row0 + 8) * SS + c];
            s[n][0] = b0v.x; s[n][1] = b0v.y; s[n][2] = b1v.x; s[n][3] = b1v.y;
        }

        // S += Q @ K^T  (scale pre-folded into Q)
        #pragma unroll
        for (int ks = 0; ks < 8; ++ks) {
            const int kk = ks * 8;
            unsigned af[4];
            af[0] = Qs[row0 * 68 + kk + t];
            af[1] = Qs[(row0 + 8) * 68 + kk + t];
            af[2] = Qs[row0 * 68 + kk + t + 4];
            af[3] = Qs[(row0 + 8) * 68 + kk + t + 4];
            #pragma unroll
            for (int n = 0; n < 8; ++n) {
                unsigned bf[2];
                bf[0] = Ks[(n * 8 + g) * 68 + kk + t];
                bf[1] = Ks[(n * 8 + g) * 68 + kk + t + 4];
                mma_tf32(s[n], af, bf);
            }
        }

        // Online softmax. Row g -> regs [0],[1]; row g+8 -> regs [2],[3].
        float mx0 = -1e30f, mx1 = -1e30f;
        #pragma unroll
        for (int n = 0; n < 8; ++n) {
            mx0 = fmaxf(mx0, fmaxf(s[n][0], s[n][1]));
            mx1 = fmaxf(mx1, fmaxf(s[n][2], s[n][3]));
        }
        #pragma unroll
        for (int x = 1; x < 4; x <<= 1) {
            mx0 = fmaxf(mx0, __shfl_xor_sync(0xffffffffu, mx0, x));
            mx1 = fmaxf(mx1, __shfl_xor_sync(0xffffffffu, mx1, x));
        }
        float mn0 = fmaxf(m0, mx0), mn1 = fmaxf(m1, mx1);
        float cr0 = __expf(m0 - mn0), cr1 = __expf(m1 - mn1);
        float ps0 = 0.f, ps1 = 0.f;
        #pragma unroll
        for (int n = 0; n < 8; ++n) {
            s[n][0] = __expf(s[n][0] - mn0); ps0 += s[n][0];
            s[n][1] = __expf(s[n][1] - mn0); ps0 += s[n][1];
            s[n][2] = __expf(s[n][2] - mn1); ps1 += s[n][2];
            s[n][3] = __expf(s[n][3] - mn1); ps1 += s[n][3];
        }
        #pragma unroll
        for (int x = 1; x < 4; x <<= 1) {
            ps0 += __shfl_xor_sync(0xffffffffu, ps0, x);
            ps1 += __shfl_xor_sync(0xffffffffu, ps1, x);
        }
        l0 = l0 * cr0 + ps0; m0 = mn0;
        l1 = l1 * cr1 + ps1; m1 = mn1;
        #pragma unroll
        for (int n = 0; n < 8; ++n) {
            o[n][0] *= cr0; o[n][1] *= cr0;
            o[n][2] *= cr1; o[n][3] *= cr1;
        }

        // P -> SMEM (reuse Ks). Sync: all warps must finish QK reads of Ks.
        __syncthreads();
        #pragma unroll
        for (int n = 0; n < 8; ++n) {
            int c = n * 8 + 2 * t;
            Ks[row0 * 68 + c]           = f2tf(s[n][0]);
            Ks[row0 * 68 + c + 1]       = f2tf(s[n][1]);
            Ks[(row0 + 8) * 68 + c]     = f2tf(s[n][2]);
            Ks[(row0 + 8) * 68 + c + 1] = f2tf(s[n][3]);
        }
        // Each warp reads back only its own P rows -> no cross-warp sync needed.

        // O += P @ V
        #pragma unroll
        for (int ks = 0; ks < 8; ++ks) {
            const int kk = ks * 8;
            unsigned af[4];
            af[0] = Ks[row0 * 68 + kk + t];
            af[1] = Ks[(row0 + 8) * 68 + kk + t];
            af[2] = Ks[row0 * 68 + kk + t + 4];
            af[3] = Ks[(row0 + 8) * 68 + kk + t + 4];
            #pragma unroll
            for (int n = 0; n < 8; ++n) {
                unsigned bf[2];
                bf[0] = Vs[(kk + t) * 68 + n * 8 + g];
                bf[1] = Vs[(kk + t + 4) * 68 + n * 8 + g];
                mma_tf32(o[n], af, bf);
            }
        }
    }

    // Normalize and write ctx as [b][s][h][d]
    float inv0 = 1.0f / l0, inv1 = 1.0f / l1;
    int q0 = qt * 64 + row0;
    float* dst0 = g_ctx + ((size_t)(b * SS + q0) * NH + h) * DH;
    float* dst1 = g_ctx + ((size_t)(b * SS + q0 + 8) * NH + h) * DH;
    #pragma unroll
    for (int n = 0; n < 8; ++n) {
        int d = n * 8 + 2 * t;
        *(float2*)&dst0[d] = make_float2(o[n][0] * inv0, o[n][1] * inv0);
        *(float2*)&dst1[d] = make_float2(o[n][2] * inv1, o[n][3] * inv1);
    }
}

// ---------------------------------------------------------------------------
extern "C" void kernel_launch(void* const* d_in, const int* in_sizes, int n_in,
                              void* d_out, int out_size)
{
    const float* x      = (const float*)d_in[0];
    const float* sinu   = (const float*)d_in[1];
    const float* abias  = (const float*)d_in[2];
    const float* qkv_w  = (const float*)d_in[3];
    const float* qkv_b  = (const float*)d_in[4];
    const float* proj_w = (const float*)d_in[5];
    float* out = (float*)d_out;

    const int flash_smem = 3 * 64 * 68 * (int)sizeof(float);  // 52224 B
    cudaFuncSetAttribute(flash_tf32,
                         cudaFuncAttributeMaxDynamicSharedMemorySize, flash_smem);

    gemm128_tf32<3 * NH * DH, true><<<dim3(24, 32), 256>>>(x, qkv_w, qkv_b, sinu, nullptr);
    flash_tf32<<<dim3(SS / 64, NH, BB), 128, flash_smem>>>(abias);
    gemm128_tf32<HID, false><<<dim3(8, 32), 256>>>(nullptr, proj_w, nullptr, nullptr, out);
}

// round 7
// speedup vs baseline: 2.7123x; 1.0324x over previous
#include <cuda_runtime.h>

// Problem constants
#define BB   2
#define SS   2048
#define HID  1024
#define NH   16
#define DH   64
#define ROT  32

// ---------------------------------------------------------------------------
// Scratch (device globals; tf32 bit patterns stored as unsigned)
// ---------------------------------------------------------------------------
__device__ unsigned g_xt[(size_t)BB * SS * HID];          // x, tf32
__device__ unsigned g_wq[(size_t)HID * 3 * NH * DH];      // qkv weights, tf32
__device__ unsigned g_wp[(size_t)HID * HID];              // proj weights, tf32
__device__ unsigned g_Q[(size_t)BB * NH * SS * DH];       // [b][h][s][d], scaled, tf32
__device__ unsigned g_K[(size_t)BB * NH * SS * DH];       // [b][h][s][d], tf32
__device__ unsigned g_Vt[(size_t)BB * NH * DH * SS];      // [b][h][d][s], tf32
__device__ unsigned g_ctx[(size_t)BB * SS * HID];         // [b][s][h*64+d], tf32

// ---------------------------------------------------------------------------
// Helpers
// ---------------------------------------------------------------------------
__device__ __forceinline__ unsigned f2tf(float x) {
    unsigned u;
    asm("cvt.rna.tf32.f32 %0, %1;" : "=r"(u) : "f"(x));
    return u;
}

__device__ __forceinline__ void mma_tf32(float* d, const unsigned* a, const unsigned* b) {
    asm volatile("mma.sync.aligned.m16n8k8.row.col.f32.tf32.tf32.f32 "
                 "{%0,%1,%2,%3}, {%4,%5,%6,%7}, {%8,%9}, {%0,%1,%2,%3};\n"
                 : "+f"(d[0]), "+f"(d[1]), "+f"(d[2]), "+f"(d[3])
                 : "r"(a[0]), "r"(a[1]), "r"(a[2]), "r"(a[3]),
                   "r"(b[0]), "r"(b[1]));
}

__device__ __forceinline__ void cp16(void* dst, const void* src) {
    unsigned d = (unsigned)__cvta_generic_to_shared(dst);
    asm volatile("cp.async.cg.shared.global [%0], [%1], 16;" :: "r"(d), "l"(src));
}
__device__ __forceinline__ void cp_commit() {
    asm volatile("cp.async.commit_group;" ::: "memory");
}
template<int N> __device__ __forceinline__ void cp_wait() {
    asm volatile("cp.async.wait_group %0;" :: "n"(N) : "memory");
}

// ldmatrix x4: four 8x4-b32 matrices -> r[0..3]; lane l receives word
// (row l>>2, col l&3) of its matrix; addresses: lanes 8m..8m+7 give the 8
// row pointers (16B rows) of matrix m.
__device__ __forceinline__ void ldsm4(unsigned r[4], const void* p) {
    unsigned a = (unsigned)__cvta_generic_to_shared(p);
    asm volatile("ldmatrix.sync.aligned.m8n8.x4.shared.b16 {%0,%1,%2,%3}, [%4];"
                 : "=r"(r[0]), "=r"(r[1]), "=r"(r[2]), "=r"(r[3]) : "r"(a));
}

// ---------------------------------------------------------------------------
// tf32 pre-convert kernels (float4 -> tf32 uint4)
// ---------------------------------------------------------------------------
template<int W>
__global__ __launch_bounds__(256) void cvt_tf32_k(const float4* __restrict__ src, int n4) {
    uint4* dst = (W == 0) ? (uint4*)g_xt : (W == 1) ? (uint4*)g_wq : (uint4*)g_wp;
    int i = blockIdx.x * 256 + threadIdx.x;
    if (i < n4) {
        float4 v = src[i];
        dst[i] = make_uint4(f2tf(v.x), f2tf(v.y), f2tf(v.z), f2tf(v.w));
    }
}

#define LDA 36    // A smem pad (rows 16B-aligned, ldmatrix conflict-free)
#define LDB 136   // B smem pad (scalar frag loads conflict-free)

// ---------------------------------------------------------------------------
// tf32 GEMM: C[4096,N] = A[4096,1024] @ W[1024,N]
// 128x128x32 tiles, 256 thr = 8 warps (2m x 4n), warp tile 64x32.
// cp.async double-buffered smem (tf32 throughout), ldmatrix A-frags.
// ---------------------------------------------------------------------------
template<int N, bool QKV_EPI>
__global__ __launch_bounds__(256, 2) void gemm_tc(
    const float* __restrict__ qbias, const float* __restrict__ sinu,
    float* __restrict__ Cout)
{
    extern __shared__ unsigned sm[];
    unsigned* As[2] = {sm, sm + 128 * LDA};
    unsigned* Bs[2] = {sm + 2 * 128 * LDA, sm + 2 * 128 * LDA + 32 * LDB};

    const int tid = threadIdx.x;
    const int lane = tid & 31, warp = tid >> 5;
    const int g = lane >> 2, t = lane & 3;
    const int quad = lane >> 3, rr = lane & 7;
    const int wm = warp >> 2, wn = warp & 3;
    const int bm = blockIdx.y * 128, bn = blockIdx.x * 128;

    const unsigned* A = QKV_EPI ? g_xt : g_ctx;
    const unsigned* W = QKV_EPI ? g_wq : g_wp;

    // per-lane ldmatrix address pieces
    const int aRow = wm * 64 + (quad & 1) * 8 + rr;
    const int aCol = (quad >> 1) * 4;

    auto loadtile = [&](int k0, int s) {
        #pragma unroll
        for (int tt = 0; tt < 4; ++tt) {
            int e = tid + tt * 256;                 // 1024 cp16 = 128x32 u32
            int r = e >> 3, c4 = (e & 7) * 4;
            cp16(&As[s][r * LDA + c4], &A[(size_t)(bm + r) * HID + k0 + c4]);
        }
        #pragma unroll
        for (int tt = 0; tt < 4; ++tt) {
            int e = tid + tt * 256;                 // 1024 cp16 = 32x128 u32
            int r = e >> 5, c4 = (e & 31) * 4;
            cp16(&Bs[s][r * LDB + c4], &W[(size_t)(k0 + r) * N + bn + c4]);
        }
        cp_commit();
    };

    float acc[4][4][4] = {};

    loadtile(0, 0);
    for (int kt = 0; kt < 32; ++kt) {
        const int s = kt & 1;
        __syncthreads();                       // all warps done with buf s^1
        if (kt + 1 < 32) { loadtile((kt + 1) * 32, s ^ 1); cp_wait<1>(); }
        else             { cp_wait<0>(); }
        __syncthreads();

        #pragma unroll
        for (int ks = 0; ks < 4; ++ks) {
            const int kk = ks * 8;
            unsigned af[4][4];
            #pragma unroll
            for (int i = 0; i < 4; ++i)
                ldsm4(af[i], &As[s][(aRow + i * 16) * LDA + kk + aCol]);
            unsigned bf[4][2];
            #pragma unroll
            for (int j = 0; j < 4; ++j) {
                int n = wn * 32 + j * 8 + g;
                bf[j][0] = Bs[s][(kk + t) * LDB + n];
                bf[j][1] = Bs[s][(kk + t + 4) * LDB + n];
            }
            #pragma unroll
            for (int i = 0; i < 4; ++i)
                #pragma unroll
                for (int j = 0; j < 4; ++j)
                    mma_tf32(acc[i][j], af[i], bf[j]);
        }
    }

    // Epilogue
    #pragma unroll
    for (int i = 0; i < 4; ++i) {
        int r0 = bm + wm * 64 + i * 16 + g;
        #pragma unroll
        for (int j = 0; j < 4; ++j) {
            int c = bn + wn * 32 + j * 8 + 2 * t;
            if (QKV_EPI) {
                #pragma unroll
                for (int e = 0; e < 4; ++e) {
                    int r = r0 + (e >> 1) * 8;
                    int cc = c + (e & 1);
                    float v = acc[i][j][e] + qbias[cc];
                    int head = cc >> 6, d = cc & 63;
                    int b = r >> 11, sx = r & (SS - 1);
                    if (head < 2 * NH && d < ROT) {
                        float sn = sinu[sx * ROT + d];
                        float cs = sinu[SS * ROT + sx * ROT + d];
                        v *= (d & 1) ? (cs + sn) : (cs - sn);
                    }
                    if (head < NH)
                        g_Q[((size_t)(b * NH + head) * SS + sx) * DH + d] = f2tf(v * 0.125f);
                    else if (head < 2 * NH)
                        g_K[((size_t)(b * NH + head - NH) * SS + sx) * DH + d] = f2tf(v);
                    else
                        g_Vt[((size_t)(b * NH + head - 2 * NH) * DH + d) * SS + sx] = f2tf(v);
                }
            } else {
                *(float2*)&Cout[(size_t)r0 * N + c] =
                    make_float2(acc[i][j][0], acc[i][j][1]);
                *(float2*)&Cout[(size_t)(r0 + 8) * N + c] =
                    make_float2(acc[i][j][2], acc[i][j][3]);
            }
        }
    }
}

// ---------------------------------------------------------------------------
// Flash attention, tf32. CTA = (q-tile 64, head, batch), 128 thr = 4 warps;
// warp w owns q rows [w*16, w*16+16). K/V cp.async double-buffered (tf32 from
// the QKV epilogue; V pre-transposed [d][s]). ldmatrix for all fragments.
// smem: Qs + Ks[2] + Vs[2] + Ps, each 64x68 u32 -> 104448 B
// ---------------------------------------------------------------------------
#define FT 4352   // 64*68
__global__ __launch_bounds__(128, 2) void flash_tc(const float* __restrict__ bias)
{
    extern __shared__ unsigned sm[];
    unsigned* Qs = sm;
    unsigned* Ks[2] = {sm + FT, sm + 2 * FT};
    unsigned* Vs[2] = {sm + 3 * FT, sm + 4 * FT};
    unsigned* Ps = sm + 5 * FT;

    const int tid = threadIdx.x, lane = tid & 31, w = tid >> 5;
    const int g = lane >> 2, t = lane & 3;
    const int quad = lane >> 3, rr = lane & 7;
    const int qt = blockIdx.x, h = blockIdx.y, b = blockIdx.z;

    const unsigned* Qg = g_Q + ((size_t)(b * NH + h) * SS + qt * 64) * DH;
    const unsigned* Kg = g_K + (size_t)(b * NH + h) * SS * DH;
    const unsigned* Vg = g_Vt + (size_t)(b * NH + h) * DH * SS;
    const float* bg = bias + ((size_t)b * SS + qt * 64) * SS;

    // ldmatrix per-lane address pieces
    const int aRow = w * 16 + (quad & 1) * 8 + rr;    // A-frag (Q / P)
    const int aCol = (quad >> 1) * 4;
    const int bRow = (quad >> 1) * 8 + rr;            // B-frag pair (K / Vt)
    const int bCol = (quad & 1) * 4;

    // FIX (round-6 bug): full 64x64 u32 tile = 1024 cp16 -> tt<8, r=e>>4,
    // c4=(e&15)*4. Round 6 issued only 256 covering cols 0..15.
    auto loadKV = [&](int kt, int s) {
        #pragma unroll
        for (int tt = 0; tt < 8; ++tt) {
            int e = tid + tt * 128;
            int r = e >> 4, c4 = (e & 15) * 4;
            cp16(&Ks[s][r * 68 + c4], &Kg[(size_t)(kt * 64 + r) * DH + c4]);
            cp16(&Vs[s][r * 68 + c4], &Vg[(size_t)r * SS + kt * 64 + c4]);
        }
        cp_commit();
    };

    // Prologue group: Q + K0 + V0 (one commit group)
    #pragma unroll
    for (int tt = 0; tt < 8; ++tt) {
        int e = tid + tt * 128;
        int r = e >> 4, c4 = (e & 15) * 4;
        cp16(&Qs[r * 68 + c4], &Qg[(size_t)r * DH + c4]);
        cp16(&Ks[0][r * 68 + c4], &Kg[(size_t)r * DH + c4]);
        cp16(&Vs[0][r * 68 + c4], &Vg[(size_t)r * SS + c4]);
    }
    cp_commit();

    const int row0 = w * 16 + g;
    float bb[8][4];
    #pragma unroll
    for (int n = 0; n < 8; ++n) {             // bias for iter 0
        int c = n * 8 + 2 * t;
        float2 x0 = __ldg((const float2*)&bg[(size_t)row0 * SS + c]);
        float2 x1 = __ldg((const float2*)&bg[(size_t)(row0 + 8) * SS + c]);
        bb[n][0] = x0.x; bb[n][1] = x0.y; bb[n][2] = x1.x; bb[n][3] = x1.y;
    }

    float m0 = -1e30f, m1 = -1e30f, l0 = 0.f, l1 = 0.f;
    float o[8][4] = {};

    for (int kt = 0; kt < SS / 64; ++kt) {
        const int s = kt & 1;
        __syncthreads();                       // done with buf s^1 everywhere
        if (kt + 1 < SS / 64) { loadKV(kt + 1, s ^ 1); cp_wait<1>(); }
        else                  { cp_wait<0>(); }
        __syncthreads();

        // S = bias; S += Q @ K^T
        float sc[8][4];
        #pragma unroll
        for (int n = 0; n < 8; ++n)
            #pragma unroll
            for (int e = 0; e < 4; ++e) sc[n][e] = bb[n][e];

        #pragma unroll
        for (int ks = 0; ks < 8; ++ks) {
            const int kk = ks * 8;
            unsigned aq[4];
            ldsm4(aq, &Qs[aRow * 68 + kk + aCol]);
            #pragma unroll
            for (int np = 0; np < 4; ++np) {
                unsigned bk[4];
                ldsm4(bk, &Ks[s][(np * 16 + bRow) * 68 + kk + bCol]);
                mma_tf32(sc[2 * np],     aq, &bk[0]);
                mma_tf32(sc[2 * np + 1], aq, &bk[2]);
            }
        }

        // prefetch bias for next iter (hides LDG under softmax+PV)
        if (kt + 1 < SS / 64) {
            #pragma unroll
            for (int n = 0; n < 8; ++n) {
                int c = (kt + 1) * 64 + n * 8 + 2 * t;
                float2 x0 = __ldg((const float2*)&bg[(size_t)row0 * SS + c]);
                float2 x1 = __ldg((const float2*)&bg[(size_t)(row0 + 8) * SS + c]);
                bb[n][0] = x0.x; bb[n][1] = x0.y; bb[n][2] = x1.x; bb[n][3] = x1.y;
            }
        }

        // Online softmax (rows g / g+8; quad-of-4 lane reductions)
        float mx0 = -1e30f, mx1 = -1e30f;
        #pragma unroll
        for (int n = 0; n < 8; ++n) {
            mx0 = fmaxf(mx0, fmaxf(sc[n][0], sc[n][1]));
            mx1 = fmaxf(mx1, fmaxf(sc[n][2], sc[n][3]));
        }
        #pragma unroll
        for (int x = 1; x < 4; x <<= 1) {
            mx0 = fmaxf(mx0, __shfl_xor_sync(0xffffffffu, mx0, x));
            mx1 = fmaxf(mx1, __shfl_xor_sync(0xffffffffu, mx1, x));
        }
        float mn0 = fmaxf(m0, mx0), mn1 = fmaxf(m1, mx1);
        float cr0 = __expf(m0 - mn0), cr1 = __expf(m1 - mn1);
        float ps0 = 0.f, ps1 = 0.f;
        #pragma unroll
        for (int n = 0; n < 8; ++n) {
            sc[n][0] = __expf(sc[n][0] - mn0); ps0 += sc[n][0];
            sc[n][1] = __expf(sc[n][1] - mn0); ps0 += sc[n][1];
            sc[n][2] = __expf(sc[n][2] - mn1); ps1 += sc[n][2];
            sc[n][3] = __expf(sc[n][3] - mn1); ps1 += sc[n][3];
        }
        #pragma unroll
        for (int x = 1; x < 4; x <<= 1) {
            ps0 += __shfl_xor_sync(0xffffffffu, ps0, x);
            ps1 += __shfl_xor_sync(0xffffffffu, ps1, x);
        }
        l0 = l0 * cr0 + ps0; m0 = mn0;
        l1 = l1 * cr1 + ps1; m1 = mn1;
        #pragma unroll
        for (int n = 0; n < 8; ++n) {
            o[n][0] *= cr0; o[n][1] *= cr0;
            o[n][2] *= cr1; o[n][3] *= cr1;
        }

        // P -> smem (warp-private rows; only intra-warp ordering needed)
        #pragma unroll
        for (int n = 0; n < 8; ++n) {
            int c = n * 8 + 2 * t;
            *(uint2*)&Ps[row0 * 68 + c] =
                make_uint2(f2tf(sc[n][0]), f2tf(sc[n][1]));
            *(uint2*)&Ps[(row0 + 8) * 68 + c] =
                make_uint2(f2tf(sc[n][2]), f2tf(sc[n][3]));
        }
        __syncwarp();

        // O += P @ V
        #pragma unroll
        for (int ks = 0; ks < 8; ++ks) {
            const int kk = ks * 8;
            unsigned ap[4];
            ldsm4(ap, &Ps[aRow * 68 + kk + aCol]);
            #pragma unroll
            for (int np = 0; np < 4; ++np) {
                unsigned bv[4];
                ldsm4(bv, &Vs[s][(np * 16 + bRow) * 68 + kk + bCol]);
                mma_tf32(o[2 * np],     ap, &bv[0]);
                mma_tf32(o[2 * np + 1], ap, &bv[2]);
            }
        }
    }

    // Normalize and write ctx (tf32) as [b][s][h][d]
    float inv0 = 1.0f / l0, inv1 = 1.0f / l1;
    int q0 = qt * 64 + row0;
    unsigned* dst0 = g_ctx + ((size_t)(b * SS + q0) * NH + h) * DH;
    unsigned* dst1 = g_ctx + ((size_t)(b * SS + q0 + 8) * NH + h) * DH;
    #pragma unroll
    for (int n = 0; n < 8; ++n) {
        int d = n * 8 + 2 * t;
        *(uint2*)&dst0[d] = make_uint2(f2tf(o[n][0] * inv0), f2tf(o[n][1] * inv0));
        *(uint2*)&dst1[d] = make_uint2(f2tf(o[n][2] * inv1), f2tf(o[n][3] * inv1));
    }
}

// ---------------------------------------------------------------------------
extern "C" void kernel_launch(void* const* d_in, const int* in_sizes, int n_in,
                              void* d_out, int out_size)
{
    const float* sinu   = (const float*)d_in[1];
    const float* abias  = (const float*)d_in[2];
    const float* qkv_b  = (const float*)d_in[4];
    float* out = (float*)d_out;

    const int gemm_smem  = (2 * 128 * LDA + 2 * 32 * LDB) * (int)sizeof(unsigned); // 71680
    const int flash_smem = 6 * FT * (int)sizeof(unsigned);                          // 104448
    cudaFuncSetAttribute(gemm_tc<3 * NH * DH, true>,
                         cudaFuncAttributeMaxDynamicSharedMemorySize, gemm_smem);
    cudaFuncSetAttribute(gemm_tc<HID, false>,
                         cudaFuncAttributeMaxDynamicSharedMemorySize, gemm_smem);
    cudaFuncSetAttribute(flash_tc,
                         cudaFuncAttributeMaxDynamicSharedMemorySize, flash_smem);

    // Pre-convert x and weights to tf32
    cvt_tf32_k<0><<<(BB * SS * HID / 4 + 255) / 256, 256>>>((const float4*)d_in[0], BB * SS * HID / 4);
    cvt_tf32_k<1><<<(HID * 3 * NH * DH / 4 + 255) / 256, 256>>>((const float4*)d_in[3], HID * 3 * NH * DH / 4);
    cvt_tf32_k<2><<<(HID * HID / 4 + 255) / 256, 256>>>((const float4*)d_in[5], HID * HID / 4);

    gemm_tc<3 * NH * DH, true><<<dim3(24, 32), 256, gemm_smem>>>(qkv_b, sinu, nullptr);
    flash_tc<<<dim3(SS / 64, NH, BB), 128, flash_smem>>>(abias);
    gemm_tc<HID, false><<<dim3(8, 32), 256, gemm_smem>>>(nullptr, nullptr, out);
    (void)in_sizes; (void)n_in; (void)out_size;
}

// round 9
// speedup vs baseline: 2.8977x; 1.0684x over previous
#include <cuda_runtime.h>

// Problem constants
#define BB   2
#define SS   2048
#define HID  1024
#define NH   16
#define DH   64
#define ROT  32

// ---------------------------------------------------------------------------
// Scratch (device globals; tf32 bit patterns stored as unsigned)
// ---------------------------------------------------------------------------
__device__ unsigned g_xt[(size_t)BB * SS * HID];          // x, tf32, [m][k]
__device__ unsigned g_wq[(size_t)3 * NH * DH * HID];      // qkv weights, tf32, TRANSPOSED [n][k]
__device__ unsigned g_wp[(size_t)HID * HID];              // proj weights, tf32, TRANSPOSED [n][k]
__device__ unsigned g_Q[(size_t)BB * NH * SS * DH];       // [b][h][s][d], scaled, tf32
__device__ unsigned g_K[(size_t)BB * NH * SS * DH];       // [b][h][s][d], tf32
__device__ unsigned g_Vt[(size_t)BB * NH * DH * SS];      // [b][h][d][s], tf32
__device__ unsigned g_ctx[(size_t)BB * SS * HID];         // [b][s][h*64+d], tf32

// ---------------------------------------------------------------------------
// Helpers
// ---------------------------------------------------------------------------
__device__ __forceinline__ unsigned f2tf(float x) {
    unsigned u;
    asm("cvt.rna.tf32.f32 %0, %1;" : "=r"(u) : "f"(x));
    return u;
}

__device__ __forceinline__ void mma_tf32(float* d, const unsigned* a, const unsigned* b) {
    asm volatile("mma.sync.aligned.m16n8k8.row.col.f32.tf32.tf32.f32 "
                 "{%0,%1,%2,%3}, {%4,%5,%6,%7}, {%8,%9}, {%0,%1,%2,%3};\n"
                 : "+f"(d[0]), "+f"(d[1]), "+f"(d[2]), "+f"(d[3])
                 : "r"(a[0]), "r"(a[1]), "r"(a[2]), "r"(a[3]),
                   "r"(b[0]), "r"(b[1]));
}

__device__ __forceinline__ void cp16(void* dst, const void* src) {
    unsigned d = (unsigned)__cvta_generic_to_shared(dst);
    asm volatile("cp.async.cg.shared.global [%0], [%1], 16;" :: "r"(d), "l"(src));
}
__device__ __forceinline__ void cp_commit() {
    asm volatile("cp.async.commit_group;" ::: "memory");
}
template<int N> __device__ __forceinline__ void cp_wait() {
    asm volatile("cp.async.wait_group %0;" :: "n"(N) : "memory");
}

// ldmatrix x4 on b32 rows: matrix m rows come from lanes 8m..8m+7 (16B rows);
// lane l receives word (row l>>2, col l&3) of each matrix.
__device__ __forceinline__ void ldsm4(unsigned r[4], const void* p) {
    unsigned a = (unsigned)__cvta_generic_to_shared(p);
    asm volatile("ldmatrix.sync.aligned.m8n8.x4.shared.b16 {%0,%1,%2,%3}, [%4];"
                 : "=r"(r[0]), "=r"(r[1]), "=r"(r[2]), "=r"(r[3]) : "r"(a));
}

// ---------------------------------------------------------------------------
// Pre-convert kernels
// ---------------------------------------------------------------------------
__global__ __launch_bounds__(256) void cvt_x_k(const float4* __restrict__ src, int n4) {
    int i = blockIdx.x * 256 + threadIdx.x;
    if (i < n4) {
        float4 v = src[i];
        ((uint4*)g_xt)[i] = make_uint4(f2tf(v.x), f2tf(v.y), f2tf(v.z), f2tf(v.w));
    }
}

// Transpose-convert: src[R][C] float -> dst[C][R] tf32.  Block (32,8), 32x32 tile.
template<int W>
__global__ __launch_bounds__(256) void cvtT_k(const float* __restrict__ src, int R, int C) {
    unsigned* dst = (W == 1) ? g_wq : g_wp;
    __shared__ float t[32][33];
    int c0 = blockIdx.x * 32, r0 = blockIdx.y * 32;
    int x = threadIdx.x, y = threadIdx.y;
    #pragma unroll
    for (int i = 0; i < 4; ++i)
        t[y + 8 * i][x] = src[(size_t)(r0 + y + 8 * i) * C + c0 + x];
    __syncthreads();
    #pragma unroll
    for (int i = 0; i < 4; ++i)
        dst[(size_t)(c0 + y + 8 * i) * R + r0 + x] = f2tf(t[x][y + 8 * i]);
}

#define LDT 36    // smem pad for 32-wide k tiles (rows 16B-aligned, ldsm conflict-free)

// ---------------------------------------------------------------------------
// tf32 GEMM: C[4096,N] = A[4096,1024] @ W^T  (W stored [n][k])
// 128x128x32 tiles, 256 thr = 8 warps (2m x 4n), warp tile 64x32.
// 3-stage cp.async pipeline, ONE barrier per k-iter, ldsm4 for A and B frags.
// ---------------------------------------------------------------------------
#define GSTG 3
template<int N, bool QKV_EPI>
__global__ __launch_bounds__(256, 2) void gemm_tc(
    const float* __restrict__ qbias, const float* __restrict__ sinu,
    float* __restrict__ Cout)
{
    extern __shared__ unsigned sm[];
    // per stage: A 128x36 + B 128x36
    unsigned* As[GSTG], *Bs[GSTG];
    #pragma unroll
    for (int i = 0; i < GSTG; ++i) {
        As[i] = sm + i * (2 * 128 * LDT);
        Bs[i] = As[i] + 128 * LDT;
    }

    const int tid = threadIdx.x;
    const int lane = tid & 31, warp = tid >> 5;
    const int g = lane >> 2, t = lane & 3;
    const int quad = lane >> 3, rr = lane & 7;
    const int wm = warp >> 2, wn = warp & 3;
    const int bm = blockIdx.y * 128, bn = blockIdx.x * 128;

    const unsigned* A = QKV_EPI ? g_xt : g_ctx;
    const unsigned* W = QKV_EPI ? g_wq : g_wp;

    const int aRow = wm * 64 + (quad & 1) * 8 + rr;   // A-frag ldsm rows
    const int aCol = (quad >> 1) * 4;
    const int bRow = (quad >> 1) * 8 + rr;            // B-frag pair ldsm rows
    const int bCol = (quad & 1) * 4;

    auto loadtile = [&](int kt, int s) {
        const int k0 = kt * 32;
        #pragma unroll
        for (int tt = 0; tt < 4; ++tt) {
            int e = tid + tt * 256;                 // 1024 cp16 = 128x32 u32
            int r = e >> 3, c4 = (e & 7) * 4;
            cp16(&As[s][r * LDT + c4], &A[(size_t)(bm + r) * HID + k0 + c4]);
        }
        #pragma unroll
        for (int tt = 0; tt < 4; ++tt) {
            int e = tid + tt * 256;                 // 1024 cp16 = 128n x 32k u32
            int r = e >> 3, c4 = (e & 7) * 4;
            cp16(&Bs[s][r * LDT + c4], &W[(size_t)(bn + r) * HID + k0 + c4]);
        }
        cp_commit();
    };

    float acc[4][4][4] = {};

    loadtile(0, 0);
    loadtile(1, 1);
    for (int kt = 0; kt < 32; ++kt) {
        const int s = kt % GSTG;
        cp_wait<1>();                 // stage kt complete (kt+1 may be pending)
        __syncthreads();              // visible to all; stage kt-1 fully consumed
        if (kt + 2 < 32) loadtile(kt + 2, (kt + 2) % GSTG);  // overwrites kt-1 slot

        #pragma unroll
        for (int ks = 0; ks < 4; ++ks) {
            const int kk = ks * 8;
            unsigned af[4][4];
            #pragma unroll
            for (int i = 0; i < 4; ++i)
                ldsm4(af[i], &As[s][(aRow + i * 16) * LDT + kk + aCol]);
            unsigned bf[2][4];        // each ldsm4 covers two 8-wide n-tiles
            #pragma unroll
            for (int jp = 0; jp < 2; ++jp)
                ldsm4(bf[jp], &Bs[s][(wn * 32 + jp * 16 + bRow) * LDT + kk + bCol]);
            #pragma unroll
            for (int i = 0; i < 4; ++i)
                #pragma unroll
                for (int j = 0; j < 4; ++j)
                    mma_tf32(acc[i][j], af[i], &bf[j >> 1][(j & 1) * 2]);
        }
    }

    // Epilogue
    #pragma unroll
    for (int i = 0; i < 4; ++i) {
        int r0 = bm + wm * 64 + i * 16 + g;
        #pragma unroll
        for (int j = 0; j < 4; ++j) {
            int c = bn + wn * 32 + j * 8 + 2 * t;
            if (QKV_EPI) {
                #pragma unroll
                for (int e = 0; e < 4; ++e) {
                    int r = r0 + (e >> 1) * 8;
                    int cc = c + (e & 1);
                    float v = acc[i][j][e] + qbias[cc];
                    int head = cc >> 6, d = cc & 63;
                    int b = r >> 11, sx = r & (SS - 1);
                    if (head < 2 * NH && d < ROT) {
                        float sn = sinu[sx * ROT + d];
                        float cs = sinu[SS * ROT + sx * ROT + d];
                        v *= (d & 1) ? (cs + sn) : (cs - sn);
                    }
                    if (head < NH)
                        g_Q[((size_t)(b * NH + head) * SS + sx) * DH + d] = f2tf(v * 0.125f);
                    else if (head < 2 * NH)
                        g_K[((size_t)(b * NH + head - NH) * SS + sx) * DH + d] = f2tf(v);
                    else
                        g_Vt[((size_t)(b * NH + head - 2 * NH) * DH + d) * SS + sx] = f2tf(v);
                }
            } else {
                *(float2*)&Cout[(size_t)r0 * N + c] =
                    make_float2(acc[i][j][0], acc[i][j][1]);
                *(float2*)&Cout[(size_t)(r0 + 8) * N + c] =
                    make_float2(acc[i][j][2], acc[i][j][3]);
            }
        }
    }
}

// ---------------------------------------------------------------------------
// Flash attention, tf32. CTA = (q-tile of 128, head, batch), 256 thr = 8 warps;
// warp w owns q rows [w*16, w*16+16). K/V 3-stage cp.async pipeline; one
// barrier per iteration. V pre-transposed [d][s]. ldmatrix everywhere.
// smem: Qs[128][68] + Ks[3]/Vs[3][64][68] + Ps[128][68] = 43520 u32 = 174080 B
// ---------------------------------------------------------------------------
#define FT  4352   // 64*68
#define FQT 8704   // 128*68
__global__ __launch_bounds__(256, 1) void flash_tc(const float* __restrict__ bias)
{
    extern __shared__ unsigned sm[];
    unsigned* Qs = sm;                                     // 128x68
    unsigned* Ks[3] = {sm + FQT, sm + FQT + FT, sm + FQT + 2 * FT};
    unsigned* Vs[3] = {sm + FQT + 3 * FT, sm + FQT + 4 * FT, sm + FQT + 5 * FT};
    unsigned* Ps = sm + FQT + 6 * FT;                      // 128x68

    const int tid = threadIdx.x, lane = tid & 31, w = tid >> 5;
    const int g = lane >> 2, t = lane & 3;
    const int quad = lane >> 3, rr = lane & 7;
    const int qt = blockIdx.x, h = blockIdx.y, b = blockIdx.z;

    const unsigned* Qg = g_Q + ((size_t)(b * NH + h) * SS + qt * 128) * DH;
    const unsigned* Kg = g_K + (size_t)(b * NH + h) * SS * DH;
    const unsigned* Vg = g_Vt + (size_t)(b * NH + h) * DH * SS;
    const float* bg = bias + ((size_t)b * SS + qt * 128) * SS;

    const int aRow = w * 16 + (quad & 1) * 8 + rr;    // A-frag (Q / P) rows
    const int aCol = (quad >> 1) * 4;
    const int bRow = (quad >> 1) * 8 + rr;            // B-frag pair (K / Vt) rows
    const int bCol = (quad & 1) * 4;

    auto loadKV = [&](int kt, int s) {
        #pragma unroll
        for (int tt = 0; tt < 4; ++tt) {
            int e = tid + tt * 256;                   // 1024 cp16 = 64x64 u32
            int r = e >> 4, c4 = (e & 15) * 4;
            cp16(&Ks[s][r * 68 + c4], &Kg[(size_t)(kt * 64 + r) * DH + c4]);
            cp16(&Vs[s][r * 68 + c4], &Vg[(size_t)r * SS + kt * 64 + c4]);
        }
        cp_commit();
    };

    // Prologue: group0 = Q + K0/V0; group1 = K1/V1
    #pragma unroll
    for (int tt = 0; tt < 8; ++tt) {
        int e = tid + tt * 256;                       // 2048 cp16 = 128x64 u32
        int r = e >> 4, c4 = (e & 15) * 4;
        cp16(&Qs[r * 68 + c4], &Qg[(size_t)r * DH + c4]);
    }
    {
        #pragma unroll
        for (int tt = 0; tt < 4; ++tt) {
            int e = tid + tt * 256;
            int r = e >> 4, c4 = (e & 15) * 4;
            cp16(&Ks[0][r * 68 + c4], &Kg[(size_t)r * DH + c4]);
            cp16(&Vs[0][r * 68 + c4], &Vg[(size_t)r * SS + c4]);
        }
        cp_commit();
    }
    loadKV(1, 1);

    const int row0 = w * 16 + g;
    float bb[8][4];
    #pragma unroll
    for (int n = 0; n < 8; ++n) {                     // bias for iter 0
        int c = n * 8 + 2 * t;
        float2 x0 = __ldg((const float2*)&bg[(size_t)row0 * SS + c]);
        float2 x1 = __ldg((const float2*)&bg[(size_t)(row0 + 8) * SS + c]);
        bb[n][0] = x0.x; bb[n][1] = x0.y; bb[n][2] = x1.x; bb[n][3] = x1.y;
    }

    float m0 = -1e30f, m1 = -1e30f, l0 = 0.f, l1 = 0.f;
    float o[8][4] = {};

    const int NT = SS / 64;
    for (int kt = 0; kt < NT; ++kt) {
        const int s = kt % 3;
        cp_wait<1>();                 // stage kt ready (kt+1 may be pending)
        __syncthreads();              // all warps done with stage kt-1
        if (kt + 2 < NT) loadKV(kt + 2, (kt + 2) % 3);

        // S = bias; S += Q @ K^T  (scale pre-folded into Q)
        float sc[8][4];
        #pragma unroll
        for (int n = 0; n < 8; ++n)
            #pragma unroll
            for (int e = 0; e < 4; ++e) sc[n][e] = bb[n][e];

        #pragma unroll
        for (int ks = 0; ks < 8; ++ks) {
            const int kk = ks * 8;
            unsigned aq[4];
            ldsm4(aq, &Qs[aRow * 68 + kk + aCol]);
            #pragma unroll
            for (int np = 0; np < 4; ++np) {
                unsigned bk[4];
                ldsm4(bk, &Ks[s][(np * 16 + bRow) * 68 + kk + bCol]);
                mma_tf32(sc[2 * np],     aq, &bk[0]);
                mma_tf32(sc[2 * np + 1], aq, &bk[2]);
            }
        }

        // prefetch bias for next iter (LDG hides under softmax + PV)
        if (kt + 1 < NT) {
            #pragma unroll
            for (int n = 0; n < 8; ++n) {
                int c = (kt + 1) * 64 + n * 8 + 2 * t;
                float2 x0 = __ldg((const float2*)&bg[(size_t)row0 * SS + c]);
                float2 x1 = __ldg((const float2*)&bg[(size_t)(row0 + 8) * SS + c]);
                bb[n][0] = x0.x; bb[n][1] = x0.y; bb[n][2] = x1.x; bb[n][3] = x1.y;
            }
        }

        // Online softmax (rows g / g+8; quad-of-4 lane reductions)
        float mx0 = -1e30f, mx1 = -1e30f;
        #pragma unroll
        for (int n = 0; n < 8; ++n) {
            mx0 = fmaxf(mx0, fmaxf(sc[n][0], sc[n][1]));
            mx1 = fmaxf(mx1, fmaxf(sc[n][2], sc[n][3]));
        }
        #pragma unroll
        for (int x = 1; x < 4; x <<= 1) {
            mx0 = fmaxf(mx0, __shfl_xor_sync(0xffffffffu, mx0, x));
            mx1 = fmaxf(mx1, __shfl_xor_sync(0xffffffffu, mx1, x));
        }
        float mn0 = fmaxf(m0, mx0), mn1 = fmaxf(m1, mx1);
        float cr0 = __expf(m0 - mn0), cr1 = __expf(m1 - mn1);
        float ps0 = 0.f, ps1 = 0.f;
        #pragma unroll
        for (int n = 0; n < 8; ++n) {
            sc[n][0] = __expf(sc[n][0] - mn0); ps0 += sc[n][0];
            sc[n][1] = __expf(sc[n][1] - mn0); ps0 += sc[n][1];
            sc[n][2] = __expf(sc[n][2] - mn1); ps1 += sc[n][2];
            sc[n][3] = __expf(sc[n][3] - mn1); ps1 += sc[n][3];
        }
        #pragma unroll
        for (int x = 1; x < 4; x <<= 1) {
            ps0 += __shfl_xor_sync(0xffffffffu, ps0, x);
            ps1 += __shfl_xor_sync(0xffffffffu, ps1, x);
        }
        l0 = l0 * cr0 + ps0; m0 = mn0;
        l1 = l1 * cr1 + ps1; m1 = mn1;
        #pragma unroll
        for (int n = 0; n < 8; ++n) {
            o[n][0] *= cr0; o[n][1] *= cr0;
            o[n][2] *= cr1; o[n][3] *= cr1;
        }

        // P -> smem (warp-private rows; only intra-warp ordering needed)
        #pragma unroll
        for (int n = 0; n < 8; ++n) {
            int c = n * 8 + 2 * t;
            *(uint2*)&Ps[row0 * 68 + c] =
                make_uint2(f2tf(sc[n][0]), f2tf(sc[n][1]));
            *(uint2*)&Ps[(row0 + 8) * 68 + c] =
                make_uint2(f2tf(sc[n][2]), f2tf(sc[n][3]));
        }
        __syncwarp();

        // O += P @ V
        #pragma unroll
        for (int ks = 0; ks < 8; ++ks) {
            const int kk = ks * 8;
            unsigned ap[4];
            ldsm4(ap, &Ps[aRow * 68 + kk + aCol]);
            #pragma unroll
            for (int np = 0; np < 4; ++np) {
                unsigned bv[4];
                ldsm4(bv, &Vs[s][(np * 16 + bRow) * 68 + kk + bCol]);
                mma_tf32(o[2 * np],     ap, &bv[0]);
                mma_tf32(o[2 * np + 1], ap, &bv[2]);
            }
        }
    }

    // Normalize and write ctx (tf32) as [b][s][h][d]
    float inv0 = 1.0f / l0, inv1 = 1.0f / l1;
    int q0 = qt * 128 + row0;
    unsigned* dst0 = g_ctx + ((size_t)(b * SS + q0) * NH + h) * DH;
    unsigned* dst1 = g_ctx + ((size_t)(b * SS + q0 + 8) * NH + h) * DH;
    #pragma unroll
    for (int n = 0; n < 8; ++n) {
        int d = n * 8 + 2 * t;
        *(uint2*)&dst0[d] = make_uint2(f2tf(o[n][0] * inv0), f2tf(o[n][1] * inv0));
        *(uint2*)&dst1[d] = make_uint2(f2tf(o[n][2] * inv1), f2tf(o[n][3] * inv1));
    }
}

// ---------------------------------------------------------------------------
extern "C" void kernel_launch(void* const* d_in, const int* in_sizes, int n_in,
                              void* d_out, int out_size)
{
    const float* sinu   = (const float*)d_in[1];
    const float* abias  = (const float*)d_in[2];
    const float* qkv_b  = (const float*)d_in[4];
    float* out = (float*)d_out;

    const int gemm_smem  = GSTG * 2 * 128 * LDT * (int)sizeof(unsigned);   // 110592
    const int flash_smem = (2 * FQT + 6 * FT) * (int)sizeof(unsigned);     // 174080
    cudaFuncSetAttribute(gemm_tc<3 * NH * DH, true>,
                         cudaFuncAttributeMaxDynamicSharedMemorySize, gemm_smem);
    cudaFuncSetAttribute(gemm_tc<HID, false>,
                         cudaFuncAttributeMaxDynamicSharedMemorySize, gemm_smem);
    cudaFuncSetAttribute(flash_tc,
                         cudaFuncAttributeMaxDynamicSharedMemorySize, flash_smem);

    // Pre-convert: x row-major tf32; weights transposed [n][k] tf32
    cvt_x_k<<<(BB * SS * HID / 4 + 255) / 256, 256>>>((const float4*)d_in[0], BB * SS * HID / 4);
    cvtT_k<1><<<dim3(3 * NH * DH / 32, HID / 32), dim3(32, 8)>>>((const float*)d_in[3], HID, 3 * NH * DH);
    cvtT_k<2><<<dim3(HID / 32, HID / 32), dim3(32, 8)>>>((const float*)d_in[5], HID, HID);

    gemm_tc<3 * NH * DH, true><<<dim3(24, 32), 256, gemm_smem>>>(qkv_b, sinu, nullptr);
    flash_tc<<<dim3(SS / 128, NH, BB), 256, flash_smem>>>(abias);
    gemm_tc<HID, false><<<dim3(8, 32), 256, gemm_smem>>>(nullptr, nullptr, out);
    (void)in_sizes; (void)n_in; (void)out_size;
}

// round 11
// speedup vs baseline: 3.1088x; 1.0729x over previous
#include <cuda_runtime.h>

// Problem constants
#define BB   2
#define SS   2048
#define HID  1024
#define NH   16
#define DH   64
#define ROT  32

// ---------------------------------------------------------------------------
// Scratch (device globals; tf32 bit patterns stored as unsigned)
// ---------------------------------------------------------------------------
__device__ unsigned g_xt[(size_t)BB * SS * HID];          // x, tf32, [m][k]
__device__ unsigned g_wq[(size_t)3 * NH * DH * HID];      // qkv weights, tf32, TRANSPOSED [n][k]
__device__ unsigned g_wp[(size_t)HID * HID];              // proj weights, tf32, TRANSPOSED [n][k]
__device__ unsigned g_Q[(size_t)BB * NH * SS * DH];       // [b][h][s][d], scaled, tf32
__device__ unsigned g_K[(size_t)BB * NH * SS * DH];       // [b][h][s][d], tf32
__device__ unsigned g_Vt[(size_t)BB * NH * DH * SS];      // [b][h][d][s], tf32
__device__ unsigned g_ctx[(size_t)BB * SS * HID];         // [b][s][h*64+d], tf32

// ---------------------------------------------------------------------------
// Helpers
// ---------------------------------------------------------------------------
__device__ __forceinline__ unsigned f2tf(float x) {
    unsigned u;
    asm("cvt.rna.tf32.f32 %0, %1;" : "=r"(u) : "f"(x));
    return u;
}

__device__ __forceinline__ void mma_tf32(float* d, const unsigned* a, const unsigned* b) {
    asm volatile("mma.sync.aligned.m16n8k8.row.col.f32.tf32.tf32.f32 "
                 "{%0,%1,%2,%3}, {%4,%5,%6,%7}, {%8,%9}, {%0,%1,%2,%3};\n"
                 : "+f"(d[0]), "+f"(d[1]), "+f"(d[2]), "+f"(d[3])
                 : "r"(a[0]), "r"(a[1]), "r"(a[2]), "r"(a[3]),
                   "r"(b[0]), "r"(b[1]));
}

__device__ __forceinline__ void cp16(void* dst, const void* src) {
    unsigned d = (unsigned)__cvta_generic_to_shared(dst);
    asm volatile("cp.async.cg.shared.global [%0], [%1], 16;" :: "r"(d), "l"(src));
}
__device__ __forceinline__ void cp_commit() {
    asm volatile("cp.async.commit_group;" ::: "memory");
}
template<int N> __device__ __forceinline__ void cp_wait() {
    asm volatile("cp.async.wait_group %0;" :: "n"(N) : "memory");
}

// ldmatrix x4 on b32 rows: matrix m rows come from lanes 8m..8m+7 (16B rows);
// lane l receives word (row l>>2, col l&3) of each matrix.
__device__ __forceinline__ void ldsm4(unsigned r[4], const void* p) {
    unsigned a = (unsigned)__cvta_generic_to_shared(p);
    asm volatile("ldmatrix.sync.aligned.m8n8.x4.shared.b16 {%0,%1,%2,%3}, [%4];"
                 : "=r"(r[0]), "=r"(r[1]), "=r"(r[2]), "=r"(r[3]) : "r"(a));
}

// ---------------------------------------------------------------------------
// Pre-convert kernels
// ---------------------------------------------------------------------------
__global__ __launch_bounds__(256) void cvt_x_k(const float4* __restrict__ src, int n4) {
    int i = blockIdx.x * 256 + threadIdx.x;
    if (i < n4) {
        float4 v = src[i];
        ((uint4*)g_xt)[i] = make_uint4(f2tf(v.x), f2tf(v.y), f2tf(v.z), f2tf(v.w));
    }
}

// Transpose-convert: src[R][C] float -> dst[C][R] tf32.  Block (32,8), 32x32 tile.
template<int W>
__global__ __launch_bounds__(256) void cvtT_k(const float* __restrict__ src, int R, int C) {
    unsigned* dst = (W == 1) ? g_wq : g_wp;
    __shared__ float t[32][33];
    int c0 = blockIdx.x * 32, r0 = blockIdx.y * 32;
    int x = threadIdx.x, y = threadIdx.y;
    #pragma unroll
    for (int i = 0; i < 4; ++i)
        t[y + 8 * i][x] = src[(size_t)(r0 + y + 8 * i) * C + c0 + x];
    __syncthreads();
    #pragma unroll
    for (int i = 0; i < 4; ++i)
        dst[(size_t)(c0 + y + 8 * i) * R + r0 + x] = f2tf(t[x][y + 8 * i]);
}

#define LDT 36    // smem pad for 32-wide k tiles (rows 16B-aligned, ldsm conflict-free)

// ---------------------------------------------------------------------------
// tf32 GEMM: C[4096,N] = A[4096,1024] @ W^T  (W stored [n][k])
// 256x128x32 tiles, 512 thr = 16 warps (4m x 4n), warp tile 64x32.
// 3-stage cp.async pipeline, ONE barrier per k-iter, ldsm4 for A and B frags.
// ---------------------------------------------------------------------------
#define GSTG 3
template<int N, bool QKV_EPI>
__global__ __launch_bounds__(512) void gemm_tc(
    const float* __restrict__ qbias, const float* __restrict__ sinu,
    float* __restrict__ Cout)
{
    extern __shared__ unsigned sm[];
    // per stage: A 256x36 + B 128x36
    unsigned* As[GSTG], *Bs[GSTG];
    #pragma unroll
    for (int i = 0; i < GSTG; ++i) {
        As[i] = sm + i * (384 * LDT);
        Bs[i] = As[i] + 256 * LDT;
    }

    const int tid = threadIdx.x;
    const int lane = tid & 31, warp = tid >> 5;
    const int g = lane >> 2, t = lane & 3;
    const int quad = lane >> 3, rr = lane & 7;
    const int wm = warp >> 2, wn = warp & 3;          // 4 (M) x 4 (N)
    const int bm = blockIdx.y * 256, bn = blockIdx.x * 128;

    const unsigned* A = QKV_EPI ? g_xt : g_ctx;
    const unsigned* W = QKV_EPI ? g_wq : g_wp;

    const int aRow = wm * 64 + (quad & 1) * 8 + rr;   // A-frag ldsm rows
    const int aCol = (quad >> 1) * 4;
    const int bRow = (quad >> 1) * 8 + rr;            // B-frag pair ldsm rows
    const int bCol = (quad & 1) * 4;

    auto loadtile = [&](int kt, int s) {
        const int k0 = kt * 32;
        #pragma unroll
        for (int tt = 0; tt < 4; ++tt) {
            int e = tid + tt * 512;                 // 2048 cp16 = 256x32 u32
            int r = e >> 3, c4 = (e & 7) * 4;
            cp16(&As[s][r * LDT + c4], &A[(size_t)(bm + r) * HID + k0 + c4]);
        }
        #pragma unroll
        for (int tt = 0; tt < 2; ++tt) {
            int e = tid + tt * 512;                 // 1024 cp16 = 128n x 32k u32
            int r = e >> 3, c4 = (e & 7) * 4;
            cp16(&Bs[s][r * LDT + c4], &W[(size_t)(bn + r) * HID + k0 + c4]);
        }
        cp_commit();
    };

    float acc[4][4][4] = {};

    loadtile(0, 0);
    loadtile(1, 1);
    for (int kt = 0; kt < 32; ++kt) {
        const int s = kt % GSTG;
        cp_wait<1>();                 // stage kt complete (kt+1 may be pending)
        __syncthreads();              // visible to all; stage kt-1 fully consumed
        if (kt + 2 < 32) loadtile(kt + 2, (kt + 2) % GSTG);  // overwrites kt-1 slot

        #pragma unroll
        for (int ks = 0; ks < 4; ++ks) {
            const int kk = ks * 8;
            unsigned af[4][4];
            #pragma unroll
            for (int i = 0; i < 4; ++i)
                ldsm4(af[i], &As[s][(aRow + i * 16) * LDT + kk + aCol]);
            unsigned bf[2][4];        // each ldsm4 covers two 8-wide n-tiles
            #pragma unroll
            for (int jp = 0; jp < 2; ++jp)
                ldsm4(bf[jp], &Bs[s][(wn * 32 + jp * 16 + bRow) * LDT + kk + bCol]);
            #pragma unroll
            for (int i = 0; i < 4; ++i)
                #pragma unroll
                for (int j = 0; j < 4; ++j)
                    mma_tf32(acc[i][j], af[i], &bf[j >> 1][(j & 1) * 2]);
        }
    }

    // Epilogue
    #pragma unroll
    for (int i = 0; i < 4; ++i) {
        int r0 = bm + wm * 64 + i * 16 + g;
        #pragma unroll
        for (int j = 0; j < 4; ++j) {
            int c = bn + wn * 32 + j * 8 + 2 * t;
            if (QKV_EPI) {
                #pragma unroll
                for (int e = 0; e < 4; ++e) {
                    int r = r0 + (e >> 1) * 8;
                    int cc = c + (e & 1);
                    float v = acc[i][j][e] + qbias[cc];
                    int head = cc >> 6, d = cc & 63;
                    int b = r >> 11, sx = r & (SS - 1);
                    if (head < 2 * NH && d < ROT) {
                        float sn = sinu[sx * ROT + d];
                        float cs = sinu[SS * ROT + sx * ROT + d];
                        v *= (d & 1) ? (cs + sn) : (cs - sn);
                    }
                    if (head < NH)
                        g_Q[((size_t)(b * NH + head) * SS + sx) * DH + d] = f2tf(v * 0.125f);
                    else if (head < 2 * NH)
                        g_K[((size_t)(b * NH + head - NH) * SS + sx) * DH + d] = f2tf(v);
                    else
                        g_Vt[((size_t)(b * NH + head - 2 * NH) * DH + d) * SS + sx] = f2tf(v);
                }
            } else {
                *(float2*)&Cout[(size_t)r0 * N + c] =
                    make_float2(acc[i][j][0], acc[i][j][1]);
                *(float2*)&Cout[(size_t)(r0 + 8) * N + c] =
                    make_float2(acc[i][j][2], acc[i][j][3]);
            }
        }
    }
}

// ---------------------------------------------------------------------------
// Flash attention, tf32. CTA = (q-tile of 256, head, batch), 512 thr = 16 warps;
// warp w owns q rows [w*16, w*16+16). K/V 2-stage cp.async pipeline (single
// outstanding group; one iteration hides one load). V pre-transposed [d][s].
// smem: Qs[256][68] + Ks[2]/Vs[2][64][68] + Ps[256][68] = 52224 u32 = 208896 B
// ---------------------------------------------------------------------------
#define FT   4352   // 64*68
#define FQT 17408   // 256*68
__global__ __launch_bounds__(512) void flash_tc(const float* __restrict__ bias)
{
    extern __shared__ unsigned sm[];
    unsigned* Qs = sm;                                     // 256x68
    unsigned* Ks[2] = {sm + FQT, sm + FQT + FT};
    unsigned* Vs[2] = {sm + FQT + 2 * FT, sm + FQT + 3 * FT};
    unsigned* Ps = sm + FQT + 4 * FT;                      // 256x68

    const int tid = threadIdx.x, lane = tid & 31, w = tid >> 5;
    const int g = lane >> 2, t = lane & 3;
    const int quad = lane >> 3, rr = lane & 7;
    const int qt = blockIdx.x, h = blockIdx.y, b = blockIdx.z;

    const unsigned* Qg = g_Q + ((size_t)(b * NH + h) * SS + qt * 256) * DH;
    const unsigned* Kg = g_K + (size_t)(b * NH + h) * SS * DH;
    const unsigned* Vg = g_Vt + (size_t)(b * NH + h) * DH * SS;
    const float* bg = bias + ((size_t)b * SS + qt * 256) * SS;

    const int aRow = w * 16 + (quad & 1) * 8 + rr;    // A-frag (Q / P) rows
    const int aCol = (quad >> 1) * 4;
    const int bRow = (quad >> 1) * 8 + rr;            // B-frag pair (K / Vt) rows
    const int bCol = (quad & 1) * 4;

    auto loadKV = [&](int kt, int s) {
        #pragma unroll
        for (int tt = 0; tt < 2; ++tt) {
            int e = tid + tt * 512;                   // 1024 cp16 = 64x64 u32
            int r = e >> 4, c4 = (e & 15) * 4;
            cp16(&Ks[s][r * 68 + c4], &Kg[(size_t)(kt * 64 + r) * DH + c4]);
            cp16(&Vs[s][r * 68 + c4], &Vg[(size_t)r * SS + kt * 64 + c4]);
        }
        cp_commit();
    };

    // Prologue: one group = Q (256x64) + K0/V0
    #pragma unroll
    for (int tt = 0; tt < 8; ++tt) {
        int e = tid + tt * 512;                       // 4096 cp16 = 256x64 u32
        int r = e >> 4, c4 = (e & 15) * 4;
        cp16(&Qs[r * 68 + c4], &Qg[(size_t)r * DH + c4]);
    }
    #pragma unroll
    for (int tt = 0; tt < 2; ++tt) {
        int e = tid + tt * 512;
        int r = e >> 4, c4 = (e & 15) * 4;
        cp16(&Ks[0][r * 68 + c4], &Kg[(size_t)r * DH + c4]);
        cp16(&Vs[0][r * 68 + c4], &Vg[(size_t)r * SS + c4]);
    }
    cp_commit();

    const int row0 = w * 16 + g;
    float m0 = -1e30f, m1 = -1e30f, l0 = 0.f, l1 = 0.f;
    float o[8][4] = {};

    const int NT = SS / 64;
    for (int kt = 0; kt < NT; ++kt) {
        const int s = kt & 1;
        cp_wait<0>();                 // stage kt ready
        __syncthreads();              // all warps done with stage kt-1 (slot s^1)
        if (kt + 1 < NT) loadKV(kt + 1, s ^ 1);

        // S = bias (LDG init; latency hidden across 16 warps); S += Q @ K^T
        float sc[8][4];
        #pragma unroll
        for (int n = 0; n < 8; ++n) {
            int c = kt * 64 + n * 8 + 2 * t;
            float2 x0 = __ldg((const float2*)&bg[(size_t)row0 * SS + c]);
            float2 x1 = __ldg((const float2*)&bg[(size_t)(row0 + 8) * SS + c]);
            sc[n][0] = x0.x; sc[n][1] = x0.y; sc[n][2] = x1.x; sc[n][3] = x1.y;
        }

        #pragma unroll
        for (int ks = 0; ks < 8; ++ks) {
            const int kk = ks * 8;
            unsigned aq[4];
            ldsm4(aq, &Qs[aRow * 68 + kk + aCol]);
            #pragma unroll
            for (int np = 0; np < 4; ++np) {
                unsigned bk[4];
                ldsm4(bk, &Ks[s][(np * 16 + bRow) * 68 + kk + bCol]);
                mma_tf32(sc[2 * np],     aq, &bk[0]);
                mma_tf32(sc[2 * np + 1], aq, &bk[2]);
            }
        }

        // Online softmax (rows g / g+8; quad-of-4 lane reductions)
        float mx0 = -1e30f, mx1 = -1e30f;
        #pragma unroll
        for (int n = 0; n < 8; ++n) {
            mx0 = fmaxf(mx0, fmaxf(sc[n][0], sc[n][1]));
            mx1 = fmaxf(mx1, fmaxf(sc[n][2], sc[n][3]));
        }
        #pragma unroll
        for (int x = 1; x < 4; x <<= 1) {
            mx0 = fmaxf(mx0, __shfl_xor_sync(0xffffffffu, mx0, x));
            mx1 = fmaxf(mx1, __shfl_xor_sync(0xffffffffu, mx1, x));
        }
        float mn0 = fmaxf(m0, mx0), mn1 = fmaxf(m1, mx1);
        float cr0 = __expf(m0 - mn0), cr1 = __expf(m1 - mn1);
        float ps0 = 0.f, ps1 = 0.f;
        #pragma unroll
        for (int n = 0; n < 8; ++n) {
            sc[n][0] = __expf(sc[n][0] - mn0); ps0 += sc[n][0];
            sc[n][1] = __expf(sc[n][1] - mn0); ps0 += sc[n][1];
            sc[n][2] = __expf(sc[n][2] - mn1); ps1 += sc[n][2];
            sc[n][3] = __expf(sc[n][3] - mn1); ps1 += sc[n][3];
        }
        #pragma unroll
        for (int x = 1; x < 4; x <<= 1) {
            ps0 += __shfl_xor_sync(0xffffffffu, ps0, x);
            ps1 += __shfl_xor_sync(0xffffffffu, ps1, x);
        }
        l0 = l0 * cr0 + ps0; m0 = mn0;
        l1 = l1 * cr1 + ps1; m1 = mn1;
        #pragma unroll
        for (int n = 0; n < 8; ++n) {
            o[n][0] *= cr0; o[n][1] *= cr0;
            o[n][2] *= cr1; o[n][3] *= cr1;
        }

        // P -> smem (warp-private rows; only intra-warp ordering needed)
        #pragma unroll
        for (int n = 0; n < 8; ++n) {
            int c = n * 8 + 2 * t;
            *(uint2*)&Ps[row0 * 68 + c] =
                make_uint2(f2tf(sc[n][0]), f2tf(sc[n][1]));
            *(uint2*)&Ps[(row0 + 8) * 68 + c] =
                make_uint2(f2tf(sc[n][2]), f2tf(sc[n][3]));
        }
        __syncwarp();

        // O += P @ V
        #pragma unroll
        for (int ks = 0; ks < 8; ++ks) {
            const int kk = ks * 8;
            unsigned ap[4];
            ldsm4(ap, &Ps[aRow * 68 + kk + aCol]);
            #pragma unroll
            for (int np = 0; np < 4; ++np) {
                unsigned bv[4];
                ldsm4(bv, &Vs[s][(np * 16 + bRow) * 68 + kk + bCol]);
                mma_tf32(o[2 * np],     ap, &bv[0]);
                mma_tf32(o[2 * np + 1], ap, &bv[2]);
            }
        }
    }

    // Normalize and write ctx (tf32) as [b][s][h][d]
    float inv0 = 1.0f / l0, inv1 = 1.0f / l1;
    int q0 = qt * 256 + row0;
    unsigned* dst0 = g_ctx + ((size_t)(b * SS + q0) * NH + h) * DH;
    unsigned* dst1 = g_ctx + ((size_t)(b * SS + q0 + 8) * NH + h) * DH;
    #pragma unroll
    for (int n = 0; n < 8; ++n) {
        int d = n * 8 + 2 * t;
        *(uint2*)&dst0[d] = make_uint2(f2tf(o[n][0] * inv0), f2tf(o[n][1] * inv0));
        *(uint2*)&dst1[d] = make_uint2(f2tf(o[n][2] * inv1), f2tf(o[n][3] * inv1));
    }
}

// ---------------------------------------------------------------------------
extern "C" void kernel_launch(void* const* d_in, const int* in_sizes, int n_in,
                              void* d_out, int out_size)
{
    const float* sinu   = (const float*)d_in[1];
    const float* abias  = (const float*)d_in[2];
    const float* qkv_b  = (const float*)d_in[4];
    float* out = (float*)d_out;

    const int gemm_smem  = GSTG * 384 * LDT * (int)sizeof(unsigned);        // 165888
    const int flash_smem = (2 * FQT + 4 * FT) * (int)sizeof(unsigned);      // 208896
    cudaFuncSetAttribute(gemm_tc<3 * NH * DH, true>,
                         cudaFuncAttributeMaxDynamicSharedMemorySize, gemm_smem);
    cudaFuncSetAttribute(gemm_tc<HID, false>,
                         cudaFuncAttributeMaxDynamicSharedMemorySize, gemm_smem);
    cudaFuncSetAttribute(flash_tc,
                         cudaFuncAttributeMaxDynamicSharedMemorySize, flash_smem);

    // Pre-convert: x row-major tf32; weights transposed [n][k] tf32
    cvt_x_k<<<(BB * SS * HID / 4 + 255) / 256, 256>>>((const float4*)d_in[0], BB * SS * HID / 4);
    cvtT_k<1><<<dim3(3 * NH * DH / 32, HID / 32), dim3(32, 8)>>>((const float*)d_in[3], HID, 3 * NH * DH);
    cvtT_k<2><<<dim3(HID / 32, HID / 32), dim3(32, 8)>>>((const float*)d_in[5], HID, HID);

    gemm_tc<3 * NH * DH, true><<<dim3(24, 16), 512, gemm_smem>>>(qkv_b, sinu, nullptr);
    flash_tc<<<dim3(SS / 256, NH, BB), 512, flash_smem>>>(abias);
    gemm_tc<HID, false><<<dim3(8, 16), 512, gemm_smem>>>(nullptr, nullptr, out);
    (void)in_sizes; (void)n_in; (void)out_size;
}